// round 6
// baseline (speedup 1.0000x reference)
#include <cuda_runtime.h>
#include <cuda_bf16.h>
#include <math.h>
#include <stdint.h>
#include <stddef.h>

#define B_ 64
#define L_ 512
#define C_ 321
#define BC 20544            // B_*C_
#define PRED_ 96
#define LP 520              // L + STRIDE
#define NB1 1284            // BC/16 blocks (k2/k4/k6)
#define CNT_BN 657408.0f    // BC*32
#define EPS_ 1e-5f

// ---------------- scratch (__device__ globals; no runtime allocation) ----------------
static __device__ float g_s[(size_t)BC * LP];        // seasonal, padded
static __device__ float g_trend[(size_t)BC * L_];    // trend rows [bc][L]
static __device__ float g_mean[BC];
static __device__ float g_std[BC];
static __device__ float g_y[(size_t)BC * 1024];      // post-LN y [bc][1024]
static __device__ float g_pool[(size_t)BC * 64];     // sp.mean(-1)
static __device__ float g_w[(size_t)BC * 64];        // gating sigmoid output
static __device__ float g_Wt[1536 * 96];             // folded weights, [k][j]
static __device__ float g_cb[96];                    // folded bias
static __device__ float g_p1s[NB1 * 64];
static __device__ float g_p1q[NB1 * 64];
static __device__ float g_p2s[NB1 * 64];
static __device__ float g_p2q[NB1 * 64];
static __device__ float g_sc1[64], g_bi1[64], g_sc2[64], g_bi2[64];

__device__ __forceinline__ float geluf(float v) {
    return 0.5f * v * (1.0f + erff(v * 0.70710678f));
}
__device__ __forceinline__ float sigf(float v) {
    return 1.0f / (1.0f + expf(-v));
}

// cp.async helpers (LDGSTS)
__device__ __forceinline__ void cpa4(uint32_t d, const float* s) {
    asm volatile("cp.async.ca.shared.global [%0], [%1], 4;\n" :: "r"(d), "l"(s));
}
__device__ __forceinline__ void cpa16(uint32_t d, const float* s) {
    asm volatile("cp.async.ca.shared.global [%0], [%1], 16;\n" :: "r"(d), "l"(s));
}
__device__ __forceinline__ void cp_commit() {
    asm volatile("cp.async.commit_group;\n" ::: "memory");
}

// ---------------- K0: fold fusion layer (merged) ----------------
__global__ void k0_fold(const float* __restrict__ seas_w, const float* __restrict__ tr_w,
                        const float* __restrict__ fus_w) {
    int bx = blockIdx.x;
    int t = threadIdx.x;
    if (bx < 384) {                                  // 96*1024 elems
        int idx = bx * 256 + t;
        int j = idx >> 10, m = idx & 1023;
        const float* fw = fus_w + j * 192;
        float a = 0.f;
        #pragma unroll 8
        for (int k = 0; k < 96; k++) a = fmaf(fw[k], seas_w[k * 1024 + m], a);
        g_Wt[m * 96 + j] = a;
    } else {                                         // 96*512 elems
        int idx = (bx - 384) * 256 + t;
        int j = idx >> 9, m = idx & 511;
        const float* fw = fus_w + j * 192 + 96;
        float a = 0.f;
        #pragma unroll 8
        for (int k = 0; k < 96; k++) a = fmaf(fw[k], tr_w[k * 512 + m], a);
        g_Wt[(1024 + m) * 96 + j] = a;
    }
}
__global__ void k0_cb(const float* __restrict__ fus_w, const float* __restrict__ fus_b,
                      const float* __restrict__ seas_b, const float* __restrict__ tr_b) {
    int j = threadIdx.x;                             // 96 threads
    float a = fus_b[j];
    for (int k = 0; k < 96; k++) {
        a = fmaf(fus_w[j * 192 + k], seas_b[k], a);
        a = fmaf(fus_w[j * 192 + 96 + k], tr_b[k], a);
    }
    g_cb[j] = a;
}

// ---------------- K1: RevIN stats + segmented-parallel EMA + seasonal/trend + pooled ----------------
__global__ void __launch_bounds__(256) k1_prep(const float* __restrict__ x,
                                               const float* __restrict__ rev_w,
                                               const float* __restrict__ rev_b) {
    extern __shared__ float sm[];
    float* xb = sm;                 // [512][33]  xn -> seasonal
    float* tb = sm + 512 * 33;      // [512][33]  trend
    __shared__ float red_s[8][33], red_q[8][33], meanb[32], stdb[32];
    __shared__ float segend[8][33], carry[8][33];
    __shared__ float pw[65];
    int b = blockIdx.y;
    int c0 = blockIdx.x * 32;
    int t = threadIdx.x;
    int w = t >> 5, lane = t & 31;
    int c = c0 + lane;
    bool cv = (c < C_);

    if (t == 0) {
        pw[0] = 1.f;
        for (int j = 1; j <= 64; j++) pw[j] = pw[j - 1] * 0.8f;
    }

    float s = 0.f, q = 0.f;
    for (int l = w; l < L_; l += 8) {
        float v = cv ? x[((size_t)b * L_ + l) * C_ + c] : 0.f;
        xb[l * 33 + lane] = v;
        s += v;
        q = fmaf(v, v, q);
    }
    red_s[w][lane] = s; red_q[w][lane] = q;
    __syncthreads();
    if (w == 0) {
        float ss = 0.f, qq = 0.f;
        #pragma unroll
        for (int i = 0; i < 8; i++) { ss += red_s[i][lane]; qq += red_q[i][lane]; }
        float mu = ss * (1.f / (float)L_);
        float v2 = fmaxf(qq - (float)L_ * mu * mu, 0.f);
        float sd = sqrtf(v2 * (1.f / (float)(L_ - 1))) + EPS_;
        meanb[lane] = mu; stdb[lane] = sd;
        if (cv) { int bc = b * C_ + c; g_mean[bc] = mu; g_std[bc] = sd; }
    }
    __syncthreads();
    {
        float rw = cv ? rev_w[c] : 1.f;
        float rb = cv ? rev_b[c] : 0.f;
        float mu = meanb[lane], inv = 1.f / stdb[lane];
        for (int l = w; l < L_; l += 8) {
            float v = xb[l * 33 + lane];
            xb[l * 33 + lane] = fmaf((v - mu) * inv, rw, rb);
        }
    }
    __syncthreads();
    // Phase A: per-(channel=lane, segment=w) provisional scan, 64 steps, carry-in 0
    {
        int base = w * 64;
        float cl;
        if (w == 0) {
            cl = xb[lane];                    // trend[0] = xn[0]
            tb[lane] = cl;
            #pragma unroll 4
            for (int l = 1; l < 64; l++) {
                cl = fmaf(0.8f, cl, 0.2f * xb[l * 33 + lane]);
                tb[l * 33 + lane] = cl;
            }
        } else {
            cl = 0.f;
            #pragma unroll 4
            for (int j = 0; j < 64; j++) {
                int l = base + j;
                cl = fmaf(0.8f, cl, 0.2f * xb[l * 33 + lane]);
                tb[l * 33 + lane] = cl;
            }
        }
        segend[w][lane] = cl;
    }
    __syncthreads();
    // Phase B: propagate carries across 8 segments per channel (warp 0)
    if (t < 32) {
        float cacc = segend[0][t];
        carry[1][t] = cacc;
        float q64 = pw[64];
        #pragma unroll
        for (int s2 = 1; s2 <= 6; s2++) {
            cacc = fmaf(q64, cacc, segend[s2][t]);
            carry[s2 + 1][t] = cacc;
        }
    }
    __syncthreads();
    // Phase C: apply correction + compute seasonal
    {
        int base = w * 64;
        float cin = (w == 0) ? 0.f : carry[w][lane];
        #pragma unroll 4
        for (int j = 0; j < 64; j++) {
            int l = base + j;
            float tf = fmaf(pw[j + 1], cin, tb[l * 33 + lane]);
            tb[l * 33 + lane] = tf;
            xb[l * 33 + lane] = xb[l * 33 + lane] - tf;
        }
    }
    __syncthreads();
    // coalesced transpose write-out + pooled
    for (int ci = w; ci < 32; ci += 8) {
        int cc = c0 + ci;
        if (cc >= C_) continue;
        size_t bc = (size_t)b * C_ + cc;
        float* gs = g_s + bc * LP;
        float* gt = g_trend + bc * (size_t)L_;
        for (int l0 = 0; l0 < L_; l0 += 32) {
            gs[l0 + lane] = xb[(l0 + lane) * 33 + ci];
            gt[l0 + lane] = tb[(l0 + lane) * 33 + ci];
        }
        if (lane < 8) gs[L_ + lane] = xb[511 * 33 + ci];
        #pragma unroll
        for (int nn = 0; nn < 2; nn++) {
            int n = 2 * lane + nn;
            float sum = 0.f;
            #pragma unroll
            for (int p = 0; p < 16; p++) {
                int l = n * 8 + p;
                if (l > 511) l = 511;
                sum += xb[l * 33 + ci];
            }
            g_pool[bc * 64 + n] = sum * (1.f / 16.f);
        }
    }
}

// ---------------- K2: bn1 partial stats of gelu(sp @ fc1^T + b1) (no tensor write) ----------------
__global__ void __launch_bounds__(256) k2_fc1(const float* __restrict__ fc1_w,
                                              const float* __restrict__ fc1_b) {
    __shared__ float s_sm[16 * LP];
    __shared__ float w_sm[512];
    __shared__ float b_sm[32];
    __shared__ float rs[256], rq[256];
    int t = threadIdx.x;
    size_t bc0 = (size_t)blockIdx.x * 16;
    w_sm[t] = fc1_w[t];
    w_sm[t + 256] = fc1_w[t + 256];
    if (t < 32) b_sm[t] = fc1_b[t];
    for (int i = t; i < 16 * LP; i += 256) s_sm[i] = g_s[bc0 * LP + i];
    __syncthreads();
    int n = t & 63;
    float psum = 0.f, psq = 0.f;
    #pragma unroll
    for (int q = 0; q < 4; q++) {
        int pair = t + 256 * q;
        int row = pair >> 6;
        const float4* sp4 = (const float4*)(s_sm + row * LP + n * 8);
        float p[16];
        #pragma unroll
        for (int v = 0; v < 4; v++) {
            float4 f = sp4[v];
            p[4 * v] = f.x; p[4 * v + 1] = f.y; p[4 * v + 2] = f.z; p[4 * v + 3] = f.w;
        }
        #pragma unroll
        for (int j = 0; j < 32; j++) {
            float acc = b_sm[j];
            const float4* wp = (const float4*)(w_sm + j * 16);
            #pragma unroll
            for (int v = 0; v < 4; v++) {
                float4 f = wp[v];
                acc = fmaf(p[4 * v], f.x, acc);
                acc = fmaf(p[4 * v + 1], f.y, acc);
                acc = fmaf(p[4 * v + 2], f.z, acc);
                acc = fmaf(p[4 * v + 3], f.w, acc);
            }
            float g = geluf(acc);
            psum += g;
            psq = fmaf(g, g, psq);
        }
    }
    rs[t] = psum; rq[t] = psq;
    __syncthreads();
    if (t < 64) {
        float S = rs[t] + rs[t + 64] + rs[t + 128] + rs[t + 192];
        float Q = rq[t] + rq[t + 64] + rq[t + 128] + rq[t + 192];
        g_p1s[blockIdx.x * 64 + t] = S;
        g_p1q[blockIdx.x * 64 + t] = Q;
    }
}

// ---------------- K3/K5: reduce bn partials (1024 threads) ----------------
__global__ void __launch_bounds__(1024) k3_stats1(const float* __restrict__ bn_w,
                                                  const float* __restrict__ bn_b) {
    __shared__ float ss[1024], qq[1024];
    int t = threadIdx.x;
    int n = t & 63, part = t >> 6;                   // 16 parts
    float s = 0.f, q = 0.f;
    for (int blk = part; blk < NB1; blk += 16) { s += g_p1s[blk * 64 + n]; q += g_p1q[blk * 64 + n]; }
    ss[t] = s; qq[t] = q;
    __syncthreads();
    if (t < 64) {
        float S = 0.f, Q = 0.f;
        #pragma unroll
        for (int i = 0; i < 16; i++) { S += ss[t + 64 * i]; Q += qq[t + 64 * i]; }
        float inv = 1.f / CNT_BN;
        float mu = S * inv;
        float var = fmaxf(Q * inv - mu * mu, 0.f);
        float sc = bn_w[t] * rsqrtf(var + EPS_);
        g_sc1[t] = sc;
        g_bi1[t] = fmaf(-mu, sc, bn_b[t]);
    }
}
__global__ void __launch_bounds__(1024) k5_stats2(const float* __restrict__ bn_w,
                                                  const float* __restrict__ bn_b) {
    __shared__ float ss[1024], qq[1024];
    int t = threadIdx.x;
    int n = t & 63, part = t >> 6;
    float s = 0.f, q = 0.f;
    for (int blk = part; blk < NB1; blk += 16) { s += g_p2s[blk * 64 + n]; q += g_p2q[blk * 64 + n]; }
    ss[t] = s; qq[t] = q;
    __syncthreads();
    if (t < 64) {
        float S = 0.f, Q = 0.f;
        #pragma unroll
        for (int i = 0; i < 16; i++) { S += ss[t + 64 * i]; Q += qq[t + 64 * i]; }
        float inv = 1.f / CNT_BN;
        float mu = S * inv;
        float var = fmaxf(Q * inv - mu * mu, 0.f);
        float sc = bn_w[t] * rsqrtf(var + EPS_);
        g_sc2[t] = sc;
        g_bi2[t] = fmaf(-mu, sc, bn_b[t]);
    }
}

// ---------------- K4: recompute fc1+gelu, bn1 affine, conv3, gelu; bn2 partials ----------------
__global__ void __launch_bounds__(256) k4_conv(const float* __restrict__ fc1_w,
                                               const float* __restrict__ fc1_b,
                                               const float* __restrict__ conv_w,
                                               const float* __restrict__ conv_b) {
    __shared__ float s_sm[16 * LP];
    __shared__ float w_sm[512];
    __shared__ float b_sm[32];
    __shared__ float rs[256], rq[256];
    int t = threadIdx.x;
    size_t bc0 = (size_t)blockIdx.x * 16;
    w_sm[t] = fc1_w[t];
    w_sm[t + 256] = fc1_w[t + 256];
    if (t < 32) b_sm[t] = fc1_b[t];
    for (int i = t; i < 16 * LP; i += 256) s_sm[i] = g_s[bc0 * LP + i];
    __syncthreads();
    int n = t & 63;
    float sc = g_sc1[n], bi = g_bi1[n];
    float c0 = conv_w[n * 3], c1 = conv_w[n * 3 + 1], c2 = conv_w[n * 3 + 2];
    float cbv = conv_b[n];
    float psum = 0.f, psq = 0.f;
    #pragma unroll
    for (int q = 0; q < 4; q++) {
        int pair = t + 256 * q;
        int row = pair >> 6;
        const float4* sp4 = (const float4*)(s_sm + row * LP + n * 8);
        float p[16];
        #pragma unroll
        for (int v = 0; v < 4; v++) {
            float4 f = sp4[v];
            p[4 * v] = f.x; p[4 * v + 1] = f.y; p[4 * v + 2] = f.z; p[4 * v + 3] = f.w;
        }
        float a[34];
        a[0] = 0.f; a[33] = 0.f;
        #pragma unroll
        for (int j = 0; j < 32; j++) {
            float acc = b_sm[j];
            const float4* wp = (const float4*)(w_sm + j * 16);
            #pragma unroll
            for (int v = 0; v < 4; v++) {
                float4 f = wp[v];
                acc = fmaf(p[4 * v], f.x, acc);
                acc = fmaf(p[4 * v + 1], f.y, acc);
                acc = fmaf(p[4 * v + 2], f.z, acc);
                acc = fmaf(p[4 * v + 3], f.w, acc);
            }
            a[j + 1] = fmaf(geluf(acc), sc, bi);
        }
        #pragma unroll
        for (int j = 0; j < 32; j++) {
            float vv = cbv;
            vv = fmaf(a[j], c0, vv);
            vv = fmaf(a[j + 1], c1, vv);
            vv = fmaf(a[j + 2], c2, vv);
            float g = geluf(vv);
            psum += g;
            psq = fmaf(g, g, psq);
        }
    }
    rs[t] = psum; rq[t] = psq;
    __syncthreads();
    if (t < 64) {
        float S = rs[t] + rs[t + 64] + rs[t + 128] + rs[t + 192];
        float Q = rq[t] + rq[t + 64] + rq[t + 128] + rq[t + 192];
        g_p2s[blockIdx.x * 64 + t] = S;
        g_p2q[blockIdx.x * 64 + t] = Q;
    }
}

// ---------------- Kg: gating MLP ----------------
__global__ void __launch_bounds__(256) kg_gate(const float* __restrict__ m1_w,
                                               const float* __restrict__ m1_b,
                                               const float* __restrict__ m2_w,
                                               const float* __restrict__ m2_b) {
    __shared__ float m2t[128 * 64];   // [h][n]
    int t = threadIdx.x;
    for (int i = t; i < 8192; i += 256) {
        int nn = i >> 7, h = i & 127;
        m2t[h * 64 + nn] = m2_w[i];
    }
    __syncthreads();
    int row = blockIdx.x * 256 + t;
    if (row >= BC) return;
    float p[64];
    const float4* pr = (const float4*)(g_pool + (size_t)row * 64);
    #pragma unroll
    for (int i = 0; i < 16; i++) {
        float4 v = pr[i];
        p[4 * i] = v.x; p[4 * i + 1] = v.y; p[4 * i + 2] = v.z; p[4 * i + 3] = v.w;
    }
    float acc[64];
    #pragma unroll
    for (int i = 0; i < 64; i++) acc[i] = 0.f;
    for (int h = 0; h < 128; h++) {
        float u = m1_b[h];
        const float4* w1 = (const float4*)(m1_w + h * 64);
        #pragma unroll
        for (int k = 0; k < 16; k++) {
            float4 v = w1[k];
            u = fmaf(p[4 * k], v.x, u);
            u = fmaf(p[4 * k + 1], v.y, u);
            u = fmaf(p[4 * k + 2], v.z, u);
            u = fmaf(p[4 * k + 3], v.w, u);
        }
        u = geluf(u);
        const float4* w2 = (const float4*)(m2t + h * 64);
        #pragma unroll
        for (int nn = 0; nn < 16; nn++) {
            float4 v = w2[nn];
            acc[4 * nn] = fmaf(u, v.x, acc[4 * nn]);
            acc[4 * nn + 1] = fmaf(u, v.y, acc[4 * nn + 1]);
            acc[4 * nn + 2] = fmaf(u, v.z, acc[4 * nn + 2]);
            acc[4 * nn + 3] = fmaf(u, v.w, acc[4 * nn + 3]);
        }
    }
    float4* dst = (float4*)(g_w + (size_t)row * 64);
    #pragma unroll
    for (int i = 0; i < 16; i++) {
        dst[i] = make_float4(sigf(acc[4 * i] + m2_b[4 * i]),
                             sigf(acc[4 * i + 1] + m2_b[4 * i + 1]),
                             sigf(acc[4 * i + 2] + m2_b[4 * i + 2]),
                             sigf(acc[4 * i + 3] + m2_b[4 * i + 3]));
    }
}

// ---------------- K6: full recompute chain + fc2 + combine + LN -> g_y ----------------
__global__ void __launch_bounds__(256) k6_local(const float* __restrict__ fc1_w,
                                                const float* __restrict__ fc1_b,
                                                const float* __restrict__ conv_w,
                                                const float* __restrict__ conv_b,
                                                const float* __restrict__ fc2_w,
                                                const float* __restrict__ fc2_b,
                                                const float* __restrict__ gl_scale,
                                                const float* __restrict__ ln_w,
                                                const float* __restrict__ ln_b) {
    __shared__ float s_sm[16 * LP];
    __shared__ float w_sm[512];       // fc1
    __shared__ float w2[512];         // fc2
    __shared__ float b_sm[32], b2[16], lw[16], lb[16];
    int t = threadIdx.x;
    size_t bc0 = (size_t)blockIdx.x * 16;
    w_sm[t] = fc1_w[t];
    w_sm[t + 256] = fc1_w[t + 256];
    w2[t] = fc2_w[t];
    w2[t + 256] = fc2_w[t + 256];
    if (t < 32) b_sm[t] = fc1_b[t];
    if (t < 16) { b2[t] = fc2_b[t]; lw[t] = ln_w[t]; lb[t] = ln_b[t]; }
    for (int i = t; i < 16 * LP; i += 256) s_sm[i] = g_s[bc0 * LP + i];
    __syncthreads();
    float gs = gl_scale[0];
    int n = t & 63;
    float sc1v = g_sc1[n], bi1v = g_bi1[n];
    float sc2v = g_sc2[n], bi2v = g_bi2[n];
    float c0 = conv_w[n * 3], c1 = conv_w[n * 3 + 1], c2 = conv_w[n * 3 + 2];
    float cbv = conv_b[n];
    #pragma unroll
    for (int q = 0; q < 4; q++) {
        int pair = t + 256 * q;
        int row = pair >> 6;
        size_t bc = bc0 + row;
        const float4* sp4 = (const float4*)(s_sm + row * LP + n * 8);
        float p[16];
        #pragma unroll
        for (int v = 0; v < 4; v++) {
            float4 f = sp4[v];
            p[4 * v] = f.x; p[4 * v + 1] = f.y; p[4 * v + 2] = f.z; p[4 * v + 3] = f.w;
        }
        // fc1 + gelu + bn1 affine
        float a[34];
        a[0] = 0.f; a[33] = 0.f;
        #pragma unroll
        for (int j = 0; j < 32; j++) {
            float acc = b_sm[j];
            const float4* wp = (const float4*)(w_sm + j * 16);
            #pragma unroll
            for (int v = 0; v < 4; v++) {
                float4 f = wp[v];
                acc = fmaf(p[4 * v], f.x, acc);
                acc = fmaf(p[4 * v + 1], f.y, acc);
                acc = fmaf(p[4 * v + 2], f.z, acc);
                acc = fmaf(p[4 * v + 3], f.w, acc);
            }
            a[j + 1] = fmaf(geluf(acc), sc1v, bi1v);
        }
        // conv3 + gelu + bn2 affine
        float h2[32];
        #pragma unroll
        for (int j = 0; j < 32; j++) {
            float vv = cbv;
            vv = fmaf(a[j], c0, vv);
            vv = fmaf(a[j + 1], c1, vv);
            vv = fmaf(a[j + 2], c2, vv);
            h2[j] = fmaf(geluf(vv), sc2v, bi2v);
        }
        // fc2 + combine + LN
        float wv = g_w[bc * 64 + n];
        float m3 = fmaf(gs, wv, 3.f);
        float y[16];
        float musum = 0.f;
        #pragma unroll
        for (int pp = 0; pp < 16; pp++) {
            float acc = b2[pp];
            const float4* wp = (const float4*)(w2 + pp * 32);
            #pragma unroll
            for (int j = 0; j < 8; j++) {
                float4 f = wp[j];
                acc = fmaf(h2[4 * j], f.x, acc);
                acc = fmaf(h2[4 * j + 1], f.y, acc);
                acc = fmaf(h2[4 * j + 2], f.z, acc);
                acc = fmaf(h2[4 * j + 3], f.w, acc);
            }
            float yy = fmaf(p[pp], m3, acc);
            y[pp] = yy;
            musum += yy;
        }
        float mu = musum * (1.f / 16.f);
        float s2 = 0.f;
        #pragma unroll
        for (int pp = 0; pp < 16; pp++) { float d = y[pp] - mu; s2 = fmaf(d, d, s2); }
        float r = rsqrtf(s2 * (1.f / 16.f) + EPS_);
        float4* gy = (float4*)(g_y + bc * 1024 + (size_t)n * 16);
        #pragma unroll
        for (int v = 0; v < 4; v++) {
            gy[v] = make_float4(fmaf((y[4 * v] - mu) * r, lw[4 * v], lb[4 * v]),
                                fmaf((y[4 * v + 1] - mu) * r, lw[4 * v + 1], lb[4 * v + 1]),
                                fmaf((y[4 * v + 2] - mu) * r, lw[4 * v + 2], lb[4 * v + 2]),
                                fmaf((y[4 * v + 3] - mu) * r, lw[4 * v + 3], lb[4 * v + 3]));
        }
    }
}

// ---------------- K7: fused final GEMM + un-RevIN + transpose ----------------
// 642 blocks = 321 row-tiles (64 rows) x 2 col-tiles (48 cols); thread tile 4x3
__global__ void __launch_bounds__(256) k7_gemm(const float* __restrict__ rev_w,
                                               const float* __restrict__ rev_b,
                                               float* __restrict__ out) {
    __shared__ float As[2][16 * 68];
    __shared__ float Bs[2][768];
    int t = threadIdx.x;
    int rb = blockIdx.x >> 1;
    int col0 = (blockIdx.x & 1) * 48;
    size_t bc0 = (size_t)rb * 64;                    // BC = 321*64 exactly
    int ty = t >> 4, tx = t & 15;
    int r0 = ty * 4, c0l = tx * 3;

    int lr = t >> 2, lk = (t & 3) * 4;
    int bk = t / 12, boff = (t % 12) * 4;

    uint32_t as_sm[2], bs_sm[2];
    as_sm[0] = (uint32_t)__cvta_generic_to_shared(&As[0][0]);
    as_sm[1] = (uint32_t)__cvta_generic_to_shared(&As[1][0]);
    bs_sm[0] = (uint32_t)__cvta_generic_to_shared(&Bs[0][0]);
    bs_sm[1] = (uint32_t)__cvta_generic_to_shared(&Bs[1][0]);

    float acc[4][3];
    #pragma unroll
    for (int i = 0; i < 4; i++)
        #pragma unroll
        for (int j = 0; j < 3; j++) acc[i][j] = 0.f;

    auto load_tile = [&](int it, int bu) {
        int k0 = it * 16;
        const float* srcrow;
        if (k0 < 1024) srcrow = g_y + (bc0 + lr) * 1024 + k0 + lk;
        else           srcrow = g_trend + (bc0 + lr) * 512 + (k0 - 1024) + lk;
        #pragma unroll
        for (int i = 0; i < 4; i++)
            cpa4(as_sm[bu] + (uint32_t)(((lk + i) * 68 + lr) * 4), srcrow + i);
        if (t < 192)
            cpa16(bs_sm[bu] + (uint32_t)(t * 16), g_Wt + (k0 + bk) * 96 + col0 + boff);
    };

    load_tile(0, 0);
    cp_commit();
    for (int it = 0; it < 96; it++) {
        int cur = it & 1;
        if (it + 1 < 96) {
            load_tile(it + 1, cur ^ 1);
            cp_commit();
            asm volatile("cp.async.wait_group 1;\n" ::: "memory");
        } else {
            asm volatile("cp.async.wait_group 0;\n" ::: "memory");
        }
        __syncthreads();
        #pragma unroll
        for (int k = 0; k < 16; k++) {
            float4 av = *(const float4*)&As[cur][k * 68 + r0];
            float b0 = Bs[cur][k * 48 + c0l];
            float b1 = Bs[cur][k * 48 + c0l + 1];
            float b2 = Bs[cur][k * 48 + c0l + 2];
            acc[0][0] = fmaf(av.x, b0, acc[0][0]);
            acc[0][1] = fmaf(av.x, b1, acc[0][1]);
            acc[0][2] = fmaf(av.x, b2, acc[0][2]);
            acc[1][0] = fmaf(av.y, b0, acc[1][0]);
            acc[1][1] = fmaf(av.y, b1, acc[1][1]);
            acc[1][2] = fmaf(av.y, b2, acc[1][2]);
            acc[2][0] = fmaf(av.z, b0, acc[2][0]);
            acc[2][1] = fmaf(av.z, b1, acc[2][1]);
            acc[2][2] = fmaf(av.z, b2, acc[2][2]);
            acc[3][0] = fmaf(av.w, b0, acc[3][0]);
            acc[3][1] = fmaf(av.w, b1, acc[3][1]);
            acc[3][2] = fmaf(av.w, b2, acc[3][2]);
        }
        __syncthreads();
    }
    #pragma unroll
    for (int i = 0; i < 4; i++) {
        size_t bc = bc0 + r0 + i;
        int b = (int)(bc / C_);
        int c = (int)(bc - (size_t)b * C_);
        float rw = rev_w[c], rb = rev_b[c];
        float sd = g_std[bc], mn = g_mean[bc];
        #pragma unroll
        for (int j = 0; j < 3; j++) {
            int col = col0 + c0l + j;
            float v = acc[i][j] + g_cb[col];
            v = fmaf((v - rb) / rw, sd, mn);
            out[((size_t)b * PRED_ + col) * C_ + c] = v;
        }
    }
}

// ---------------- launch ----------------
extern "C" void kernel_launch(void* const* d_in, const int* in_sizes, int n_in,
                              void* d_out, int out_size) {
    const float* x       = (const float*)d_in[0];
    const float* rev_w   = (const float*)d_in[1];
    const float* rev_b   = (const float*)d_in[2];
    const float* fc1_w   = (const float*)d_in[3];
    const float* fc1_b   = (const float*)d_in[4];
    const float* bn1_w   = (const float*)d_in[5];
    const float* bn1_b   = (const float*)d_in[6];
    const float* conv_w  = (const float*)d_in[7];
    const float* conv_b  = (const float*)d_in[8];
    const float* bn2_w   = (const float*)d_in[9];
    const float* bn2_b   = (const float*)d_in[10];
    const float* fc2_w   = (const float*)d_in[11];
    const float* fc2_b   = (const float*)d_in[12];
    const float* m1_w    = (const float*)d_in[13];
    const float* m1_b    = (const float*)d_in[14];
    const float* m2_w    = (const float*)d_in[15];
    const float* m2_b    = (const float*)d_in[16];
    const float* gl_sc   = (const float*)d_in[17];
    const float* ln_w    = (const float*)d_in[18];
    const float* ln_b    = (const float*)d_in[19];
    const float* seas_w  = (const float*)d_in[20];
    const float* seas_b  = (const float*)d_in[21];
    const float* tr_w    = (const float*)d_in[22];
    const float* tr_b    = (const float*)d_in[23];
    const float* fus_w   = (const float*)d_in[24];
    const float* fus_b   = (const float*)d_in[25];
    float* out = (float*)d_out;

    const int K1_SMEM = 512 * 33 * 2 * sizeof(float);   // 135168
    cudaFuncSetAttribute(k1_prep, cudaFuncAttributeMaxDynamicSharedMemorySize, K1_SMEM);

    k0_fold<<<576, 256>>>(seas_w, tr_w, fus_w);
    k0_cb<<<1, 96>>>(fus_w, fus_b, seas_b, tr_b);
    k1_prep<<<dim3(11, 64), 256, K1_SMEM>>>(x, rev_w, rev_b);
    k2_fc1<<<NB1, 256>>>(fc1_w, fc1_b);
    k3_stats1<<<1, 1024>>>(bn1_w, bn1_b);
    k4_conv<<<NB1, 256>>>(fc1_w, fc1_b, conv_w, conv_b);
    k5_stats2<<<1, 1024>>>(bn2_w, bn2_b);
    kg_gate<<<81, 256>>>(m1_w, m1_b, m2_w, m2_b);
    k6_local<<<NB1, 256>>>(fc1_w, fc1_b, conv_w, conv_b, fc2_w, fc2_b, gl_sc, ln_w, ln_b);
    k7_gemm<<<642, 256>>>(rev_w, rev_b, out);
    (void)in_sizes; (void)n_in; (void)out_size;
}

// round 7
// speedup vs baseline: 1.9092x; 1.9092x over previous
#include <cuda_runtime.h>
#include <cuda_bf16.h>
#include <math.h>
#include <stdint.h>
#include <stddef.h>

#define B_ 64
#define L_ 512
#define C_ 321
#define BC 20544            // B_*C_
#define PRED_ 96
#define LP 520              // L + STRIDE
#define NB1 1284            // BC/16 blocks (k4/k6)
#define NBK1 704            // 11*64 k1 blocks
#define CNT_BN 657408.0f    // BC*32
#define EPS_ 1e-5f

// ---------------- scratch (__device__ globals; no runtime allocation) ----------------
static __device__ float g_s[(size_t)BC * LP];        // seasonal, padded
static __device__ float g_trend[(size_t)BC * L_];    // trend rows [bc][L]
static __device__ float g_mean[BC];
static __device__ float g_std[BC];
static __device__ float g_h[(size_t)BC * 2048];      // h1 = gelu(fc1), layout [bc][j(32)][n(64)]
static __device__ float g_y[(size_t)BC * 1024];      // post-LN y [bc][1024]
static __device__ float g_pool[(size_t)BC * 64];     // sp.mean(-1)
static __device__ float g_w[(size_t)BC * 64];        // gating sigmoid output
static __device__ float g_Wt[1536 * 96];             // folded weights, [k][j]
static __device__ float g_cb[96];                    // folded bias
static __device__ float g_p1s[NBK1 * 64];
static __device__ float g_p1q[NBK1 * 64];
static __device__ float g_p2s[NB1 * 64];
static __device__ float g_p2q[NB1 * 64];
static __device__ float g_sc1[64], g_bi1[64], g_sc2[64], g_bi2[64];

__device__ __forceinline__ float geluf(float v) {
    return 0.5f * v * (1.0f + erff(v * 0.70710678f));
}
__device__ __forceinline__ float sigf(float v) {
    return 1.0f / (1.0f + expf(-v));
}

// cp.async helpers (LDGSTS)
__device__ __forceinline__ void cpa4(uint32_t d, const float* s) {
    asm volatile("cp.async.ca.shared.global [%0], [%1], 4;\n" :: "r"(d), "l"(s));
}
__device__ __forceinline__ void cpa16(uint32_t d, const float* s) {
    asm volatile("cp.async.ca.shared.global [%0], [%1], 16;\n" :: "r"(d), "l"(s));
}
__device__ __forceinline__ void cp_commit() {
    asm volatile("cp.async.commit_group;\n" ::: "memory");
}

// ---------------- K0: fold fusion layer ----------------
__global__ void k0_fold(const float* __restrict__ seas_w, const float* __restrict__ tr_w,
                        const float* __restrict__ fus_w) {
    int bx = blockIdx.x;
    int t = threadIdx.x;
    if (bx < 384) {
        int idx = bx * 256 + t;
        int j = idx >> 10, m = idx & 1023;
        const float* fw = fus_w + j * 192;
        float a = 0.f;
        #pragma unroll 8
        for (int k = 0; k < 96; k++) a = fmaf(fw[k], seas_w[k * 1024 + m], a);
        g_Wt[m * 96 + j] = a;
    } else {
        int idx = (bx - 384) * 256 + t;
        int j = idx >> 9, m = idx & 511;
        const float* fw = fus_w + j * 192 + 96;
        float a = 0.f;
        #pragma unroll 8
        for (int k = 0; k < 96; k++) a = fmaf(fw[k], tr_w[k * 512 + m], a);
        g_Wt[(1024 + m) * 96 + j] = a;
    }
}
__global__ void k0_cb(const float* __restrict__ fus_w, const float* __restrict__ fus_b,
                      const float* __restrict__ seas_b, const float* __restrict__ tr_b) {
    int j = threadIdx.x;
    float a = fus_b[j];
    for (int k = 0; k < 96; k++) {
        a = fmaf(fus_w[j * 192 + k], seas_b[k], a);
        a = fmaf(fus_w[j * 192 + 96 + k], tr_b[k], a);
    }
    g_cb[j] = a;
}

// ---------------- K1: RevIN + EMA + seasonal/trend + pooled + fc1/gelu + bn1 partials ----------------
// grid (11, 64); 256 threads; dynamic smem 135168
__global__ void __launch_bounds__(256) k1_prep(const float* __restrict__ x,
                                               const float* __restrict__ rev_w,
                                               const float* __restrict__ rev_b,
                                               const float* __restrict__ fc1_w,
                                               const float* __restrict__ fc1_b) {
    extern __shared__ float sm[];
    float* xb = sm;                 // [512][33]  xn -> seasonal
    float* tb = sm + 512 * 33;      // [512][33]  trend; later reused as h staging
    __shared__ float red_s[8][33], red_q[8][33], meanb[32], stdb[32];
    __shared__ float segend[8][33], carry[8][33];
    __shared__ float pw[65];
    __shared__ float w_sm[512], b_sm[32];
    __shared__ float rs1[256], rq1[256];
    int b = blockIdx.y;
    int c0 = blockIdx.x * 32;
    int t = threadIdx.x;
    int w = t >> 5, lane = t & 31;
    int c = c0 + lane;
    bool cv = (c < C_);

    if (t == 0) {
        pw[0] = 1.f;
        for (int j = 1; j <= 64; j++) pw[j] = pw[j - 1] * 0.8f;
    }
    w_sm[t] = fc1_w[t];
    w_sm[t + 256] = fc1_w[t + 256];
    if (t < 32) b_sm[t] = fc1_b[t];

    float s = 0.f, q = 0.f;
    for (int l = w; l < L_; l += 8) {
        float v = cv ? x[((size_t)b * L_ + l) * C_ + c] : 0.f;
        xb[l * 33 + lane] = v;
        s += v;
        q = fmaf(v, v, q);
    }
    red_s[w][lane] = s; red_q[w][lane] = q;
    __syncthreads();
    if (w == 0) {
        float ss = 0.f, qq = 0.f;
        #pragma unroll
        for (int i = 0; i < 8; i++) { ss += red_s[i][lane]; qq += red_q[i][lane]; }
        float mu = ss * (1.f / (float)L_);
        float v2 = fmaxf(qq - (float)L_ * mu * mu, 0.f);
        float sd = sqrtf(v2 * (1.f / (float)(L_ - 1))) + EPS_;
        meanb[lane] = mu; stdb[lane] = sd;
        if (cv) { int bc = b * C_ + c; g_mean[bc] = mu; g_std[bc] = sd; }
    }
    __syncthreads();
    {
        float rw = cv ? rev_w[c] : 1.f;
        float rb = cv ? rev_b[c] : 0.f;
        float mu = meanb[lane], inv = 1.f / stdb[lane];
        for (int l = w; l < L_; l += 8) {
            float v = xb[l * 33 + lane];
            xb[l * 33 + lane] = fmaf((v - mu) * inv, rw, rb);
        }
    }
    __syncthreads();
    // segmented EMA scan
    {
        int base = w * 64;
        float cl;
        if (w == 0) {
            cl = xb[lane];
            tb[lane] = cl;
            #pragma unroll 4
            for (int l = 1; l < 64; l++) {
                cl = fmaf(0.8f, cl, 0.2f * xb[l * 33 + lane]);
                tb[l * 33 + lane] = cl;
            }
        } else {
            cl = 0.f;
            #pragma unroll 4
            for (int j = 0; j < 64; j++) {
                int l = base + j;
                cl = fmaf(0.8f, cl, 0.2f * xb[l * 33 + lane]);
                tb[l * 33 + lane] = cl;
            }
        }
        segend[w][lane] = cl;
    }
    __syncthreads();
    if (t < 32) {
        float cacc = segend[0][t];
        carry[1][t] = cacc;
        float q64 = pw[64];
        #pragma unroll
        for (int s2 = 1; s2 <= 6; s2++) {
            cacc = fmaf(q64, cacc, segend[s2][t]);
            carry[s2 + 1][t] = cacc;
        }
    }
    __syncthreads();
    {
        int base = w * 64;
        float cin = (w == 0) ? 0.f : carry[w][lane];
        #pragma unroll 4
        for (int j = 0; j < 64; j++) {
            int l = base + j;
            float tf = fmaf(pw[j + 1], cin, tb[l * 33 + lane]);
            tb[l * 33 + lane] = tf;
            xb[l * 33 + lane] = xb[l * 33 + lane] - tf;
        }
    }
    __syncthreads();
    // write-out: seasonal, trend, pooled (uses tb, xb)
    for (int ci = w; ci < 32; ci += 8) {
        int cc = c0 + ci;
        if (cc >= C_) continue;
        size_t bc = (size_t)b * C_ + cc;
        float* gs = g_s + bc * LP;
        float* gt = g_trend + bc * (size_t)L_;
        for (int l0 = 0; l0 < L_; l0 += 32) {
            gs[l0 + lane] = xb[(l0 + lane) * 33 + ci];
            gt[l0 + lane] = tb[(l0 + lane) * 33 + ci];
        }
        if (lane < 8) gs[L_ + lane] = xb[511 * 33 + ci];
        #pragma unroll
        for (int nn = 0; nn < 2; nn++) {
            int n = 2 * lane + nn;
            float sum = 0.f;
            #pragma unroll
            for (int p = 0; p < 16; p++) {
                int l = n * 8 + p;
                if (l > 511) l = 511;
                sum += xb[l * 33 + ci];
            }
            g_pool[bc * 64 + n] = sum * (1.f / 16.f);
        }
    }
    __syncthreads();
    // fc1 + gelu: 4 chunks of 8 channels; stage into tb [ci8][j(32)][n(64)], then coalesced store
    float psum = 0.f, psq = 0.f;
    int nfix = t & 63;
    for (int chunk = 0; chunk < 4; chunk++) {
        #pragma unroll
        for (int r = 0; r < 2; r++) {
            int pair = t + 256 * r;
            int ci_l = pair >> 6;                    // 0..7
            int ci = chunk * 8 + ci_l;
            bool valid = (c0 + ci < C_);
            float pv[16];
            #pragma unroll
            for (int p = 0; p < 16; p++) {
                int idx = nfix * 8 + p;
                if (idx > 511) idx = 511;
                pv[p] = xb[idx * 33 + ci];
            }
            #pragma unroll
            for (int j = 0; j < 32; j++) {
                float acc = b_sm[j];
                const float4* wp = (const float4*)(w_sm + j * 16);
                #pragma unroll
                for (int v = 0; v < 4; v++) {
                    float4 f = wp[v];
                    acc = fmaf(pv[4 * v], f.x, acc);
                    acc = fmaf(pv[4 * v + 1], f.y, acc);
                    acc = fmaf(pv[4 * v + 2], f.z, acc);
                    acc = fmaf(pv[4 * v + 3], f.w, acc);
                }
                float g = geluf(acc);
                if (valid) { psum += g; psq = fmaf(g, g, psq); }
                tb[ci_l * 2048 + j * 64 + nfix] = g;
            }
        }
        __syncthreads();
        for (int i = t; i < 8 * 2048; i += 256) {
            int ci_l = i >> 11;
            int cc = c0 + chunk * 8 + ci_l;
            if (cc < C_)
                g_h[((size_t)b * C_ + cc) * 2048 + (i & 2047)] = tb[i];
        }
        __syncthreads();
    }
    rs1[t] = psum; rq1[t] = psq;
    __syncthreads();
    if (t < 64) {
        float S = rs1[t] + rs1[t + 64] + rs1[t + 128] + rs1[t + 192];
        float Q = rq1[t] + rq1[t + 64] + rq1[t + 128] + rq1[t + 192];
        int blk = blockIdx.y * 11 + blockIdx.x;
        g_p1s[blk * 64 + t] = S;
        g_p1q[blk * 64 + t] = Q;
    }
}

// ---------------- K3/K5: reduce bn partials ----------------
__global__ void __launch_bounds__(1024) k3_stats1(const float* __restrict__ bn_w,
                                                  const float* __restrict__ bn_b) {
    __shared__ float ss[1024], qq[1024];
    int t = threadIdx.x;
    int n = t & 63, part = t >> 6;
    float s = 0.f, q = 0.f;
    for (int blk = part; blk < NBK1; blk += 16) { s += g_p1s[blk * 64 + n]; q += g_p1q[blk * 64 + n]; }
    ss[t] = s; qq[t] = q;
    __syncthreads();
    if (t < 64) {
        float S = 0.f, Q = 0.f;
        #pragma unroll
        for (int i = 0; i < 16; i++) { S += ss[t + 64 * i]; Q += qq[t + 64 * i]; }
        float inv = 1.f / CNT_BN;
        float mu = S * inv;
        float var = fmaxf(Q * inv - mu * mu, 0.f);
        float sc = bn_w[t] * rsqrtf(var + EPS_);
        g_sc1[t] = sc;
        g_bi1[t] = fmaf(-mu, sc, bn_b[t]);
    }
}
__global__ void __launch_bounds__(1024) k5_stats2(const float* __restrict__ bn_w,
                                                  const float* __restrict__ bn_b) {
    __shared__ float ss[1024], qq[1024];
    int t = threadIdx.x;
    int n = t & 63, part = t >> 6;
    float s = 0.f, q = 0.f;
    for (int blk = part; blk < NB1; blk += 16) { s += g_p2s[blk * 64 + n]; q += g_p2q[blk * 64 + n]; }
    ss[t] = s; qq[t] = q;
    __syncthreads();
    if (t < 64) {
        float S = 0.f, Q = 0.f;
        #pragma unroll
        for (int i = 0; i < 16; i++) { S += ss[t + 64 * i]; Q += qq[t + 64 * i]; }
        float inv = 1.f / CNT_BN;
        float mu = S * inv;
        float var = fmaxf(Q * inv - mu * mu, 0.f);
        float sc = bn_w[t] * rsqrtf(var + EPS_);
        g_sc2[t] = sc;
        g_bi2[t] = fmaf(-mu, sc, bn_b[t]);
    }
}

// ---------------- K4: read g_h, bn1 affine + conv3 + gelu; bn2 partials ----------------
__global__ void __launch_bounds__(256) k4_conv(const float* __restrict__ conv_w,
                                               const float* __restrict__ conv_b) {
    __shared__ float rs[256], rq[256];
    int t = threadIdx.x;
    size_t bc0 = (size_t)blockIdx.x * 16;
    int n = t & 63;
    float sc = g_sc1[n], bi = g_bi1[n];
    float c0 = conv_w[n * 3], c1 = conv_w[n * 3 + 1], c2 = conv_w[n * 3 + 2];
    float cbv = conv_b[n];
    float psum = 0.f, psq = 0.f;
    #pragma unroll
    for (int q = 0; q < 4; q++) {
        int pair = t + 256 * q;
        int row = pair >> 6;
        const float* hp = g_h + (bc0 + row) * 2048 + n;
        float a[34];
        a[0] = 0.f; a[33] = 0.f;
        #pragma unroll
        for (int j = 0; j < 32; j++) a[j + 1] = fmaf(hp[j * 64], sc, bi);
        #pragma unroll
        for (int j = 0; j < 32; j++) {
            float vv = cbv;
            vv = fmaf(a[j], c0, vv);
            vv = fmaf(a[j + 1], c1, vv);
            vv = fmaf(a[j + 2], c2, vv);
            float g = geluf(vv);
            psum += g;
            psq = fmaf(g, g, psq);
        }
    }
    rs[t] = psum; rq[t] = psq;
    __syncthreads();
    if (t < 64) {
        float S = rs[t] + rs[t + 64] + rs[t + 128] + rs[t + 192];
        float Q = rq[t] + rq[t + 64] + rq[t + 128] + rq[t + 192];
        g_p2s[blockIdx.x * 64 + t] = S;
        g_p2q[blockIdx.x * 64 + t] = Q;
    }
}

// ---------------- Kg: gating MLP, warp-per-row ----------------
// dynamic smem: m1p [128][65] | m2t [128][64] | ps [8][64] | us [8][128]
__global__ void __launch_bounds__(256) kg_gate(const float* __restrict__ m1_w,
                                               const float* __restrict__ m1_b,
                                               const float* __restrict__ m2_w,
                                               const float* __restrict__ m2_b) {
    extern __shared__ float kg_sm[];
    float* m1p = kg_sm;                 // 8320
    float* m2t = kg_sm + 8320;          // 8192
    float* ps  = kg_sm + 16512;         // 512
    float* us  = kg_sm + 17024;         // 1024
    int t = threadIdx.x;
    int w = t >> 5, lane = t & 31;
    size_t bc0 = (size_t)blockIdx.x * 8;
    for (int i = t; i < 8192; i += 256) {
        int h = i >> 6, k = i & 63;
        m1p[h * 65 + k] = m1_w[i];
    }
    for (int i = t; i < 8192; i += 256) {
        int nn = i >> 7, h = i & 127;
        m2t[h * 64 + nn] = m2_w[i];
    }
    for (int i = t; i < 512; i += 256)
        ps[i] = g_pool[bc0 * 64 + i];
    __syncthreads();
    // each warp: one row; lane computes u[lane], u[lane+32], u[lane+64], u[lane+96]
    const float* pr = ps + w * 64;
    float u0 = m1_b[lane], u1 = m1_b[lane + 32], u2 = m1_b[lane + 64], u3 = m1_b[lane + 96];
    #pragma unroll 8
    for (int k = 0; k < 64; k++) {
        float pk = pr[k];
        u0 = fmaf(pk, m1p[lane * 65 + k], u0);
        u1 = fmaf(pk, m1p[(lane + 32) * 65 + k], u1);
        u2 = fmaf(pk, m1p[(lane + 64) * 65 + k], u2);
        u3 = fmaf(pk, m1p[(lane + 96) * 65 + k], u3);
    }
    float* uw = us + w * 128;
    uw[lane] = geluf(u0);
    uw[lane + 32] = geluf(u1);
    uw[lane + 64] = geluf(u2);
    uw[lane + 96] = geluf(u3);
    __syncwarp();
    float a0 = m2_b[lane], a1 = m2_b[lane + 32];
    #pragma unroll 8
    for (int h = 0; h < 128; h++) {
        float uh = uw[h];
        a0 = fmaf(uh, m2t[h * 64 + lane], a0);
        a1 = fmaf(uh, m2t[h * 64 + lane + 32], a1);
    }
    g_w[(bc0 + w) * 64 + lane] = sigf(a0);
    g_w[(bc0 + w) * 64 + lane + 32] = sigf(a1);
}

// ---------------- K6: read g_h, chain conv/bn2/fc2 + combine + LN -> g_y ----------------
__global__ void __launch_bounds__(256) k6_local(const float* __restrict__ conv_w,
                                                const float* __restrict__ conv_b,
                                                const float* __restrict__ fc2_w,
                                                const float* __restrict__ fc2_b,
                                                const float* __restrict__ gl_scale,
                                                const float* __restrict__ ln_w,
                                                const float* __restrict__ ln_b) {
    __shared__ float s_sm[16 * LP];
    __shared__ float w2[512], b2[16], lw[16], lb[16];
    int t = threadIdx.x;
    size_t bc0 = (size_t)blockIdx.x * 16;
    w2[t] = fc2_w[t];
    w2[t + 256] = fc2_w[t + 256];
    if (t < 16) { b2[t] = fc2_b[t]; lw[t] = ln_w[t]; lb[t] = ln_b[t]; }
    for (int i = t; i < 16 * LP; i += 256) s_sm[i] = g_s[bc0 * LP + i];
    __syncthreads();
    float gs = gl_scale[0];
    int n = t & 63;
    float sc1v = g_sc1[n], bi1v = g_bi1[n];
    float sc2v = g_sc2[n], bi2v = g_bi2[n];
    float c0 = conv_w[n * 3], c1 = conv_w[n * 3 + 1], c2 = conv_w[n * 3 + 2];
    float cbv = conv_b[n];
    #pragma unroll
    for (int q = 0; q < 4; q++) {
        int pair = t + 256 * q;
        int row = pair >> 6;
        size_t bc = bc0 + row;
        const float* hp = g_h + bc * 2048 + n;
        float a[34];
        a[0] = 0.f; a[33] = 0.f;
        #pragma unroll
        for (int j = 0; j < 32; j++) a[j + 1] = fmaf(hp[j * 64], sc1v, bi1v);
        // in-place conv3+gelu+bn2 (carry = original left neighbor)
        float left = 0.f;
        #pragma unroll
        for (int j = 0; j < 32; j++) {
            float cur = a[j + 1];
            float vv = cbv;
            vv = fmaf(left, c0, vv);
            vv = fmaf(cur, c1, vv);
            vv = fmaf(a[j + 2], c2, vv);
            left = cur;
            a[j + 1] = fmaf(geluf(vv), sc2v, bi2v);
        }
        float p[16];
        const float4* spp = (const float4*)(s_sm + row * LP + n * 8);
        #pragma unroll
        for (int v = 0; v < 4; v++) {
            float4 f = spp[v];
            p[4 * v] = f.x; p[4 * v + 1] = f.y; p[4 * v + 2] = f.z; p[4 * v + 3] = f.w;
        }
        float wv = g_w[bc * 64 + n];
        float m3 = fmaf(gs, wv, 3.f);
        float y[16];
        float musum = 0.f;
        #pragma unroll
        for (int pp = 0; pp < 16; pp++) {
            float acc = b2[pp];
            const float4* wp = (const float4*)(w2 + pp * 32);
            #pragma unroll
            for (int j = 0; j < 8; j++) {
                float4 f = wp[j];
                acc = fmaf(a[4 * j + 1], f.x, acc);
                acc = fmaf(a[4 * j + 2], f.y, acc);
                acc = fmaf(a[4 * j + 3], f.z, acc);
                acc = fmaf(a[4 * j + 4], f.w, acc);
            }
            float yy = fmaf(p[pp], m3, acc);
            y[pp] = yy;
            musum += yy;
        }
        float mu = musum * (1.f / 16.f);
        float s2 = 0.f;
        #pragma unroll
        for (int pp = 0; pp < 16; pp++) { float d = y[pp] - mu; s2 = fmaf(d, d, s2); }
        float r = rsqrtf(s2 * (1.f / 16.f) + EPS_);
        float4* gy = (float4*)(g_y + bc * 1024 + (size_t)n * 16);
        #pragma unroll
        for (int v = 0; v < 4; v++) {
            gy[v] = make_float4(fmaf((y[4 * v] - mu) * r, lw[4 * v], lb[4 * v]),
                                fmaf((y[4 * v + 1] - mu) * r, lw[4 * v + 1], lb[4 * v + 1]),
                                fmaf((y[4 * v + 2] - mu) * r, lw[4 * v + 2], lb[4 * v + 2]),
                                fmaf((y[4 * v + 3] - mu) * r, lw[4 * v + 3], lb[4 * v + 3]));
        }
    }
}

// ---------------- K7: fused final GEMM + un-RevIN + transpose ----------------
__global__ void __launch_bounds__(256) k7_gemm(const float* __restrict__ rev_w,
                                               const float* __restrict__ rev_b,
                                               float* __restrict__ out) {
    __shared__ float As[2][16 * 68];
    __shared__ float Bs[2][768];
    int t = threadIdx.x;
    int rb = blockIdx.x >> 1;
    int col0 = (blockIdx.x & 1) * 48;
    size_t bc0 = (size_t)rb * 64;
    int ty = t >> 4, tx = t & 15;
    int r0 = ty * 4, c0l = tx * 3;

    int lr = t >> 2, lk = (t & 3) * 4;
    int bk = t / 12, boff = (t % 12) * 4;

    uint32_t as_sm[2], bs_sm[2];
    as_sm[0] = (uint32_t)__cvta_generic_to_shared(&As[0][0]);
    as_sm[1] = (uint32_t)__cvta_generic_to_shared(&As[1][0]);
    bs_sm[0] = (uint32_t)__cvta_generic_to_shared(&Bs[0][0]);
    bs_sm[1] = (uint32_t)__cvta_generic_to_shared(&Bs[1][0]);

    float acc[4][3];
    #pragma unroll
    for (int i = 0; i < 4; i++)
        #pragma unroll
        for (int j = 0; j < 3; j++) acc[i][j] = 0.f;

    auto load_tile = [&](int it, int bu) {
        int k0 = it * 16;
        const float* srcrow;
        if (k0 < 1024) srcrow = g_y + (bc0 + lr) * 1024 + k0 + lk;
        else           srcrow = g_trend + (bc0 + lr) * 512 + (k0 - 1024) + lk;
        #pragma unroll
        for (int i = 0; i < 4; i++)
            cpa4(as_sm[bu] + (uint32_t)(((lk + i) * 68 + lr) * 4), srcrow + i);
        if (t < 192)
            cpa16(bs_sm[bu] + (uint32_t)(t * 16), g_Wt + (k0 + bk) * 96 + col0 + boff);
    };

    load_tile(0, 0);
    cp_commit();
    for (int it = 0; it < 96; it++) {
        int cur = it & 1;
        if (it + 1 < 96) {
            load_tile(it + 1, cur ^ 1);
            cp_commit();
            asm volatile("cp.async.wait_group 1;\n" ::: "memory");
        } else {
            asm volatile("cp.async.wait_group 0;\n" ::: "memory");
        }
        __syncthreads();
        #pragma unroll
        for (int k = 0; k < 16; k++) {
            float4 av = *(const float4*)&As[cur][k * 68 + r0];
            float b0 = Bs[cur][k * 48 + c0l];
            float b1 = Bs[cur][k * 48 + c0l + 1];
            float b2 = Bs[cur][k * 48 + c0l + 2];
            acc[0][0] = fmaf(av.x, b0, acc[0][0]);
            acc[0][1] = fmaf(av.x, b1, acc[0][1]);
            acc[0][2] = fmaf(av.x, b2, acc[0][2]);
            acc[1][0] = fmaf(av.y, b0, acc[1][0]);
            acc[1][1] = fmaf(av.y, b1, acc[1][1]);
            acc[1][2] = fmaf(av.y, b2, acc[1][2]);
            acc[2][0] = fmaf(av.z, b0, acc[2][0]);
            acc[2][1] = fmaf(av.z, b1, acc[2][1]);
            acc[2][2] = fmaf(av.z, b2, acc[2][2]);
            acc[3][0] = fmaf(av.w, b0, acc[3][0]);
            acc[3][1] = fmaf(av.w, b1, acc[3][1]);
            acc[3][2] = fmaf(av.w, b2, acc[3][2]);
        }
        __syncthreads();
    }
    #pragma unroll
    for (int i = 0; i < 4; i++) {
        size_t bc = bc0 + r0 + i;
        int b = (int)(bc / C_);
        int c = (int)(bc - (size_t)b * C_);
        float rw = rev_w[c], rb = rev_b[c];
        float sd = g_std[bc], mn = g_mean[bc];
        #pragma unroll
        for (int j = 0; j < 3; j++) {
            int col = col0 + c0l + j;
            float v = acc[i][j] + g_cb[col];
            v = fmaf((v - rb) / rw, sd, mn);
            out[((size_t)b * PRED_ + col) * C_ + c] = v;
        }
    }
}

// ---------------- launch ----------------
extern "C" void kernel_launch(void* const* d_in, const int* in_sizes, int n_in,
                              void* d_out, int out_size) {
    const float* x       = (const float*)d_in[0];
    const float* rev_w   = (const float*)d_in[1];
    const float* rev_b   = (const float*)d_in[2];
    const float* fc1_w   = (const float*)d_in[3];
    const float* fc1_b   = (const float*)d_in[4];
    const float* bn1_w   = (const float*)d_in[5];
    const float* bn1_b   = (const float*)d_in[6];
    const float* conv_w  = (const float*)d_in[7];
    const float* conv_b  = (const float*)d_in[8];
    const float* bn2_w   = (const float*)d_in[9];
    const float* bn2_b   = (const float*)d_in[10];
    const float* fc2_w   = (const float*)d_in[11];
    const float* fc2_b   = (const float*)d_in[12];
    const float* m1_w    = (const float*)d_in[13];
    const float* m1_b    = (const float*)d_in[14];
    const float* m2_w    = (const float*)d_in[15];
    const float* m2_b    = (const float*)d_in[16];
    const float* gl_sc   = (const float*)d_in[17];
    const float* ln_w    = (const float*)d_in[18];
    const float* ln_b    = (const float*)d_in[19];
    const float* seas_w  = (const float*)d_in[20];
    const float* seas_b  = (const float*)d_in[21];
    const float* tr_w    = (const float*)d_in[22];
    const float* tr_b    = (const float*)d_in[23];
    const float* fus_w   = (const float*)d_in[24];
    const float* fus_b   = (const float*)d_in[25];
    float* out = (float*)d_out;

    const int K1_SMEM = 512 * 33 * 2 * sizeof(float);   // 135168
    const int KG_SMEM = 18048 * sizeof(float);           // 72192
    cudaFuncSetAttribute(k1_prep, cudaFuncAttributeMaxDynamicSharedMemorySize, K1_SMEM);
    cudaFuncSetAttribute(kg_gate, cudaFuncAttributeMaxDynamicSharedMemorySize, KG_SMEM);

    k1_prep<<<dim3(11, 64), 256, K1_SMEM>>>(x, rev_w, rev_b, fc1_w, fc1_b);
    k3_stats1<<<1, 1024>>>(bn1_w, bn1_b);
    k4_conv<<<NB1, 256>>>(conv_w, conv_b);
    k5_stats2<<<1, 1024>>>(bn2_w, bn2_b);
    kg_gate<<<2568, 256, KG_SMEM>>>(m1_w, m1_b, m2_w, m2_b);
    k6_local<<<NB1, 256>>>(conv_w, conv_b, fc2_w, fc2_b, gl_sc, ln_w, ln_b);
    k0_fold<<<576, 256>>>(seas_w, tr_w, fus_w);
    k0_cb<<<1, 96>>>(fus_w, fus_b, seas_b, tr_b);
    k7_gemm<<<642, 256>>>(rev_w, rev_b, out);
    (void)in_sizes; (void)n_in; (void)out_size;
}

// round 8
// speedup vs baseline: 1.9874x; 1.0410x over previous
#include <cuda_runtime.h>
#include <cuda_bf16.h>
#include <math.h>
#include <stdint.h>
#include <stddef.h>

#define B_ 64
#define L_ 512
#define C_ 321
#define BC 20544            // B_*C_
#define PRED_ 96
#define LP 520              // L + STRIDE
#define NB1 1284            // BC/16 blocks (k4/k6)
#define NBK1 704            // 11*64 k1 blocks
#define CNT_BN 657408.0f    // BC*32
#define EPS_ 1e-5f

// ---------------- scratch (__device__ globals; no runtime allocation) ----------------
static __device__ float g_s[(size_t)BC * LP];        // seasonal, padded
static __device__ float g_trend[(size_t)BC * L_];    // trend rows [bc][L]
static __device__ float g_mean[BC];
static __device__ float g_std[BC];
static __device__ float g_h[(size_t)BC * 2048];      // h1 = gelu(fc1), layout [bc][j(32)][n(64)]
static __device__ float g_y[(size_t)BC * 1024];      // post-LN y [bc][1024]
static __device__ float g_pool[(size_t)BC * 64];     // sp.mean(-1)
static __device__ float g_w[(size_t)BC * 64];        // gating sigmoid output
static __device__ float g_Wt[1536 * 96];             // folded weights, [k][j]
static __device__ float g_cb[96];                    // folded bias
static __device__ float g_p1s[NBK1 * 64];
static __device__ float g_p1q[NBK1 * 64];
static __device__ float g_p2s[NB1 * 64];
static __device__ float g_p2q[NB1 * 64];
static __device__ float g_sc1[64], g_bi1[64], g_sc2[64], g_bi2[64];

__device__ __forceinline__ float geluf(float v) {
    return 0.5f * v * (1.0f + erff(v * 0.70710678f));
}
__device__ __forceinline__ float sigf(float v) {
    return 1.0f / (1.0f + expf(-v));
}

// cp.async helpers (LDGSTS)
__device__ __forceinline__ void cpa4(uint32_t d, const float* s) {
    asm volatile("cp.async.ca.shared.global [%0], [%1], 4;\n" :: "r"(d), "l"(s));
}
__device__ __forceinline__ void cpa16(uint32_t d, const float* s) {
    asm volatile("cp.async.ca.shared.global [%0], [%1], 16;\n" :: "r"(d), "l"(s));
}
__device__ __forceinline__ void cp_commit() {
    asm volatile("cp.async.commit_group;\n" ::: "memory");
}

// ---------------- K0: fold fusion layer (3 launches so k1 is launch #4) ----------------
__global__ void k0_fold1(const float* __restrict__ seas_w, const float* __restrict__ fus_w) {
    int idx = blockIdx.x * 256 + threadIdx.x;       // 96*1024
    int j = idx >> 10, m = idx & 1023;
    const float* fw = fus_w + j * 192;
    float a = 0.f;
    #pragma unroll 8
    for (int k = 0; k < 96; k++) a = fmaf(fw[k], seas_w[k * 1024 + m], a);
    g_Wt[m * 96 + j] = a;
}
__global__ void k0_fold2(const float* __restrict__ tr_w, const float* __restrict__ fus_w) {
    int idx = blockIdx.x * 256 + threadIdx.x;       // 96*512
    int j = idx >> 9, m = idx & 511;
    const float* fw = fus_w + j * 192 + 96;
    float a = 0.f;
    #pragma unroll 8
    for (int k = 0; k < 96; k++) a = fmaf(fw[k], tr_w[k * 512 + m], a);
    g_Wt[(1024 + m) * 96 + j] = a;
}
__global__ void k0_cb(const float* __restrict__ fus_w, const float* __restrict__ fus_b,
                      const float* __restrict__ seas_b, const float* __restrict__ tr_b) {
    int j = threadIdx.x;
    float a = fus_b[j];
    for (int k = 0; k < 96; k++) {
        a = fmaf(fus_w[j * 192 + k], seas_b[k], a);
        a = fmaf(fus_w[j * 192 + 96 + k], tr_b[k], a);
    }
    g_cb[j] = a;
}

// ---------------- K1: RevIN + EMA + seasonal/trend + pooled + fc1/gelu + bn1 partials ----------------
__global__ void __launch_bounds__(256) k1_prep(const float* __restrict__ x,
                                               const float* __restrict__ rev_w,
                                               const float* __restrict__ rev_b,
                                               const float* __restrict__ fc1_w,
                                               const float* __restrict__ fc1_b) {
    extern __shared__ float sm[];
    float* xb = sm;                 // [512][33]  xn -> seasonal
    float* tb = sm + 512 * 33;      // [512][33]  trend; later reused as h staging
    __shared__ float red_s[8][33], red_q[8][33], meanb[32], stdb[32];
    __shared__ float segend[8][33], carry[8][33];
    __shared__ float pw[65];
    __shared__ float w_sm[512], b_sm[32];
    __shared__ float rs1[256], rq1[256];
    int b = blockIdx.y;
    int c0 = blockIdx.x * 32;
    int t = threadIdx.x;
    int w = t >> 5, lane = t & 31;
    int c = c0 + lane;
    bool cv = (c < C_);

    if (t == 0) {
        pw[0] = 1.f;
        for (int j = 1; j <= 64; j++) pw[j] = pw[j - 1] * 0.8f;
    }
    w_sm[t] = fc1_w[t];
    w_sm[t + 256] = fc1_w[t + 256];
    if (t < 32) b_sm[t] = fc1_b[t];

    float s = 0.f, q = 0.f;
    for (int l = w; l < L_; l += 8) {
        float v = cv ? x[((size_t)b * L_ + l) * C_ + c] : 0.f;
        xb[l * 33 + lane] = v;
        s += v;
        q = fmaf(v, v, q);
    }
    red_s[w][lane] = s; red_q[w][lane] = q;
    __syncthreads();
    if (w == 0) {
        float ss = 0.f, qq = 0.f;
        #pragma unroll
        for (int i = 0; i < 8; i++) { ss += red_s[i][lane]; qq += red_q[i][lane]; }
        float mu = ss * (1.f / (float)L_);
        float v2 = fmaxf(qq - (float)L_ * mu * mu, 0.f);
        float sd = sqrtf(v2 * (1.f / (float)(L_ - 1))) + EPS_;
        meanb[lane] = mu; stdb[lane] = sd;
        if (cv) { int bc = b * C_ + c; g_mean[bc] = mu; g_std[bc] = sd; }
    }
    __syncthreads();
    {
        float rw = cv ? rev_w[c] : 1.f;
        float rb = cv ? rev_b[c] : 0.f;
        float mu = meanb[lane], inv = 1.f / stdb[lane];
        for (int l = w; l < L_; l += 8) {
            float v = xb[l * 33 + lane];
            xb[l * 33 + lane] = fmaf((v - mu) * inv, rw, rb);
        }
    }
    __syncthreads();
    // segmented EMA scan
    {
        int base = w * 64;
        float cl;
        if (w == 0) {
            cl = xb[lane];
            tb[lane] = cl;
            #pragma unroll 4
            for (int l = 1; l < 64; l++) {
                cl = fmaf(0.8f, cl, 0.2f * xb[l * 33 + lane]);
                tb[l * 33 + lane] = cl;
            }
        } else {
            cl = 0.f;
            #pragma unroll 4
            for (int j = 0; j < 64; j++) {
                int l = base + j;
                cl = fmaf(0.8f, cl, 0.2f * xb[l * 33 + lane]);
                tb[l * 33 + lane] = cl;
            }
        }
        segend[w][lane] = cl;
    }
    __syncthreads();
    if (t < 32) {
        float cacc = segend[0][t];
        carry[1][t] = cacc;
        float q64 = pw[64];
        #pragma unroll
        for (int s2 = 1; s2 <= 6; s2++) {
            cacc = fmaf(q64, cacc, segend[s2][t]);
            carry[s2 + 1][t] = cacc;
        }
    }
    __syncthreads();
    {
        int base = w * 64;
        float cin = (w == 0) ? 0.f : carry[w][lane];
        #pragma unroll 4
        for (int j = 0; j < 64; j++) {
            int l = base + j;
            float tf = fmaf(pw[j + 1], cin, tb[l * 33 + lane]);
            tb[l * 33 + lane] = tf;
            xb[l * 33 + lane] = xb[l * 33 + lane] - tf;
        }
    }
    __syncthreads();
    // write-out: seasonal, trend, pooled
    for (int ci = w; ci < 32; ci += 8) {
        int cc = c0 + ci;
        if (cc >= C_) continue;
        size_t bc = (size_t)b * C_ + cc;
        float* gs = g_s + bc * LP;
        float* gt = g_trend + bc * (size_t)L_;
        for (int l0 = 0; l0 < L_; l0 += 32) {
            gs[l0 + lane] = xb[(l0 + lane) * 33 + ci];
            gt[l0 + lane] = tb[(l0 + lane) * 33 + ci];
        }
        if (lane < 8) gs[L_ + lane] = xb[511 * 33 + ci];
        #pragma unroll
        for (int nn = 0; nn < 2; nn++) {
            int n = 2 * lane + nn;
            float sum = 0.f;
            #pragma unroll
            for (int p = 0; p < 16; p++) {
                int l = n * 8 + p;
                if (l > 511) l = 511;
                sum += xb[l * 33 + ci];
            }
            g_pool[bc * 64 + n] = sum * (1.f / 16.f);
        }
    }
    __syncthreads();
    // fc1 + gelu: 4 chunks of 8 channels; stage into tb [ci8][j(32)][n(64)], then coalesced store
    float psum = 0.f, psq = 0.f;
    int nfix = t & 63;
    for (int chunk = 0; chunk < 4; chunk++) {
        #pragma unroll
        for (int r = 0; r < 2; r++) {
            int pair = t + 256 * r;
            int ci_l = pair >> 6;                    // 0..7
            int ci = chunk * 8 + ci_l;
            bool valid = (c0 + ci < C_);
            float pv[16];
            #pragma unroll
            for (int p = 0; p < 16; p++) {
                int idx = nfix * 8 + p;
                if (idx > 511) idx = 511;
                pv[p] = xb[idx * 33 + ci];
            }
            #pragma unroll
            for (int j = 0; j < 32; j++) {
                float acc = b_sm[j];
                const float4* wp = (const float4*)(w_sm + j * 16);
                #pragma unroll
                for (int v = 0; v < 4; v++) {
                    float4 f = wp[v];
                    acc = fmaf(pv[4 * v], f.x, acc);
                    acc = fmaf(pv[4 * v + 1], f.y, acc);
                    acc = fmaf(pv[4 * v + 2], f.z, acc);
                    acc = fmaf(pv[4 * v + 3], f.w, acc);
                }
                float g = geluf(acc);
                if (valid) { psum += g; psq = fmaf(g, g, psq); }
                tb[ci_l * 2048 + j * 64 + nfix] = g;
            }
        }
        __syncthreads();
        for (int i = t; i < 8 * 2048; i += 256) {
            int ci_l = i >> 11;
            int cc = c0 + chunk * 8 + ci_l;
            if (cc < C_)
                g_h[((size_t)b * C_ + cc) * 2048 + (i & 2047)] = tb[i];
        }
        __syncthreads();
    }
    rs1[t] = psum; rq1[t] = psq;
    __syncthreads();
    if (t < 64) {
        float S = rs1[t] + rs1[t + 64] + rs1[t + 128] + rs1[t + 192];
        float Q = rq1[t] + rq1[t + 64] + rq1[t + 128] + rq1[t + 192];
        int blk = blockIdx.y * 11 + blockIdx.x;
        g_p1s[blk * 64 + t] = S;
        g_p1q[blk * 64 + t] = Q;
    }
}

// ---------------- K3/K5: reduce bn partials ----------------
__global__ void __launch_bounds__(1024) k3_stats1(const float* __restrict__ bn_w,
                                                  const float* __restrict__ bn_b) {
    __shared__ float ss[1024], qq[1024];
    int t = threadIdx.x;
    int n = t & 63, part = t >> 6;
    float s = 0.f, q = 0.f;
    for (int blk = part; blk < NBK1; blk += 16) { s += g_p1s[blk * 64 + n]; q += g_p1q[blk * 64 + n]; }
    ss[t] = s; qq[t] = q;
    __syncthreads();
    if (t < 64) {
        float S = 0.f, Q = 0.f;
        #pragma unroll
        for (int i = 0; i < 16; i++) { S += ss[t + 64 * i]; Q += qq[t + 64 * i]; }
        float inv = 1.f / CNT_BN;
        float mu = S * inv;
        float var = fmaxf(Q * inv - mu * mu, 0.f);
        float sc = bn_w[t] * rsqrtf(var + EPS_);
        g_sc1[t] = sc;
        g_bi1[t] = fmaf(-mu, sc, bn_b[t]);
    }
}
__global__ void __launch_bounds__(1024) k5_stats2(const float* __restrict__ bn_w,
                                                  const float* __restrict__ bn_b) {
    __shared__ float ss[1024], qq[1024];
    int t = threadIdx.x;
    int n = t & 63, part = t >> 6;
    float s = 0.f, q = 0.f;
    for (int blk = part; blk < NB1; blk += 16) { s += g_p2s[blk * 64 + n]; q += g_p2q[blk * 64 + n]; }
    ss[t] = s; qq[t] = q;
    __syncthreads();
    if (t < 64) {
        float S = 0.f, Q = 0.f;
        #pragma unroll
        for (int i = 0; i < 16; i++) { S += ss[t + 64 * i]; Q += qq[t + 64 * i]; }
        float inv = 1.f / CNT_BN;
        float mu = S * inv;
        float var = fmaxf(Q * inv - mu * mu, 0.f);
        float sc = bn_w[t] * rsqrtf(var + EPS_);
        g_sc2[t] = sc;
        g_bi2[t] = fmaf(-mu, sc, bn_b[t]);
    }
}

// ---------------- K4: read g_h, bn1 affine + conv3 + gelu; bn2 partials ----------------
__global__ void __launch_bounds__(256) k4_conv(const float* __restrict__ conv_w,
                                               const float* __restrict__ conv_b) {
    __shared__ float rs[256], rq[256];
    int t = threadIdx.x;
    size_t bc0 = (size_t)blockIdx.x * 16;
    int n = t & 63;
    float sc = g_sc1[n], bi = g_bi1[n];
    float c0 = conv_w[n * 3], c1 = conv_w[n * 3 + 1], c2 = conv_w[n * 3 + 2];
    float cbv = conv_b[n];
    float psum = 0.f, psq = 0.f;
    #pragma unroll
    for (int q = 0; q < 4; q++) {
        int pair = t + 256 * q;
        int row = pair >> 6;
        const float* hp = g_h + (bc0 + row) * 2048 + n;
        float a[34];
        a[0] = 0.f; a[33] = 0.f;
        #pragma unroll
        for (int j = 0; j < 32; j++) a[j + 1] = fmaf(hp[j * 64], sc, bi);
        #pragma unroll
        for (int j = 0; j < 32; j++) {
            float vv = cbv;
            vv = fmaf(a[j], c0, vv);
            vv = fmaf(a[j + 1], c1, vv);
            vv = fmaf(a[j + 2], c2, vv);
            float g = geluf(vv);
            psum += g;
            psq = fmaf(g, g, psq);
        }
    }
    rs[t] = psum; rq[t] = psq;
    __syncthreads();
    if (t < 64) {
        float S = rs[t] + rs[t + 64] + rs[t + 128] + rs[t + 192];
        float Q = rq[t] + rq[t + 64] + rq[t + 128] + rq[t + 192];
        g_p2s[blockIdx.x * 64 + t] = S;
        g_p2q[blockIdx.x * 64 + t] = Q;
    }
}

// ---------------- Kg: gating MLP, warp-per-row, 32 rows/block ----------------
// dynamic smem: m1p [128][65] | m2t [128][64] | ps [32][64] | us [8][128]
__global__ void __launch_bounds__(256) kg_gate(const float* __restrict__ m1_w,
                                               const float* __restrict__ m1_b,
                                               const float* __restrict__ m2_w,
                                               const float* __restrict__ m2_b) {
    extern __shared__ float kg_sm[];
    float* m1p = kg_sm;                 // 8320
    float* m2t = kg_sm + 8320;          // 8192
    float* ps  = kg_sm + 16512;         // 2048
    float* us  = kg_sm + 18560;         // 1024
    int t = threadIdx.x;
    int w = t >> 5, lane = t & 31;
    size_t bc0 = (size_t)blockIdx.x * 32;
    for (int i = t; i < 8192; i += 256) {
        int h = i >> 6, k = i & 63;
        m1p[h * 65 + k] = m1_w[i];
    }
    for (int i = t; i < 8192; i += 256) {
        int nn = i >> 7, h = i & 127;
        m2t[h * 64 + nn] = m2_w[i];
    }
    for (int i = t; i < 2048; i += 256)
        ps[i] = g_pool[bc0 * 64 + i];
    __syncthreads();
    float* uw = us + w * 128;
    #pragma unroll
    for (int rr = 0; rr < 4; rr++) {
        int rloc = rr * 8 + w;
        const float* pr = ps + rloc * 64;
        float u0 = m1_b[lane], u1 = m1_b[lane + 32], u2 = m1_b[lane + 64], u3 = m1_b[lane + 96];
        #pragma unroll 8
        for (int k = 0; k < 64; k++) {
            float pk = pr[k];
            u0 = fmaf(pk, m1p[lane * 65 + k], u0);
            u1 = fmaf(pk, m1p[(lane + 32) * 65 + k], u1);
            u2 = fmaf(pk, m1p[(lane + 64) * 65 + k], u2);
            u3 = fmaf(pk, m1p[(lane + 96) * 65 + k], u3);
        }
        uw[lane] = geluf(u0);
        uw[lane + 32] = geluf(u1);
        uw[lane + 64] = geluf(u2);
        uw[lane + 96] = geluf(u3);
        __syncwarp();
        float a0 = m2_b[lane], a1 = m2_b[lane + 32];
        #pragma unroll 8
        for (int h = 0; h < 128; h++) {
            float uh = uw[h];
            a0 = fmaf(uh, m2t[h * 64 + lane], a0);
            a1 = fmaf(uh, m2t[h * 64 + lane + 32], a1);
        }
        g_w[(bc0 + rloc) * 64 + lane] = sigf(a0);
        g_w[(bc0 + rloc) * 64 + lane + 32] = sigf(a1);
        __syncwarp();
    }
}

// ---------------- K6: read g_h, chain conv/bn2/fc2 + combine + LN -> g_y ----------------
__global__ void __launch_bounds__(256) k6_local(const float* __restrict__ conv_w,
                                                const float* __restrict__ conv_b,
                                                const float* __restrict__ fc2_w,
                                                const float* __restrict__ fc2_b,
                                                const float* __restrict__ gl_scale,
                                                const float* __restrict__ ln_w,
                                                const float* __restrict__ ln_b) {
    __shared__ float s_sm[16 * LP];
    __shared__ float w2[512], b2[16], lw[16], lb[16];
    int t = threadIdx.x;
    size_t bc0 = (size_t)blockIdx.x * 16;
    w2[t] = fc2_w[t];
    w2[t + 256] = fc2_w[t + 256];
    if (t < 16) { b2[t] = fc2_b[t]; lw[t] = ln_w[t]; lb[t] = ln_b[t]; }
    for (int i = t; i < 16 * LP; i += 256) s_sm[i] = g_s[bc0 * LP + i];
    __syncthreads();
    float gs = gl_scale[0];
    int n = t & 63;
    float sc1v = g_sc1[n], bi1v = g_bi1[n];
    float sc2v = g_sc2[n], bi2v = g_bi2[n];
    float c0 = conv_w[n * 3], c1 = conv_w[n * 3 + 1], c2 = conv_w[n * 3 + 2];
    float cbv = conv_b[n];
    #pragma unroll
    for (int q = 0; q < 4; q++) {
        int pair = t + 256 * q;
        int row = pair >> 6;
        size_t bc = bc0 + row;
        const float* hp = g_h + bc * 2048 + n;
        float a[34];
        a[0] = 0.f; a[33] = 0.f;
        #pragma unroll
        for (int j = 0; j < 32; j++) a[j + 1] = fmaf(hp[j * 64], sc1v, bi1v);
        float left = 0.f;
        #pragma unroll
        for (int j = 0; j < 32; j++) {
            float cur = a[j + 1];
            float vv = cbv;
            vv = fmaf(left, c0, vv);
            vv = fmaf(cur, c1, vv);
            vv = fmaf(a[j + 2], c2, vv);
            left = cur;
            a[j + 1] = fmaf(geluf(vv), sc2v, bi2v);
        }
        float p[16];
        const float4* spp = (const float4*)(s_sm + row * LP + n * 8);
        #pragma unroll
        for (int v = 0; v < 4; v++) {
            float4 f = spp[v];
            p[4 * v] = f.x; p[4 * v + 1] = f.y; p[4 * v + 2] = f.z; p[4 * v + 3] = f.w;
        }
        float wv = g_w[bc * 64 + n];
        float m3 = fmaf(gs, wv, 3.f);
        float y[16];
        float musum = 0.f;
        #pragma unroll
        for (int pp = 0; pp < 16; pp++) {
            float acc = b2[pp];
            const float4* wp = (const float4*)(w2 + pp * 32);
            #pragma unroll
            for (int j = 0; j < 8; j++) {
                float4 f = wp[j];
                acc = fmaf(a[4 * j + 1], f.x, acc);
                acc = fmaf(a[4 * j + 2], f.y, acc);
                acc = fmaf(a[4 * j + 3], f.z, acc);
                acc = fmaf(a[4 * j + 4], f.w, acc);
            }
            float yy = fmaf(p[pp], m3, acc);
            y[pp] = yy;
            musum += yy;
        }
        float mu = musum * (1.f / 16.f);
        float s2 = 0.f;
        #pragma unroll
        for (int pp = 0; pp < 16; pp++) { float d = y[pp] - mu; s2 = fmaf(d, d, s2); }
        float r = rsqrtf(s2 * (1.f / 16.f) + EPS_);
        float4* gy = (float4*)(g_y + bc * 1024 + (size_t)n * 16);
        #pragma unroll
        for (int v = 0; v < 4; v++) {
            gy[v] = make_float4(fmaf((y[4 * v] - mu) * r, lw[4 * v], lb[4 * v]),
                                fmaf((y[4 * v + 1] - mu) * r, lw[4 * v + 1], lb[4 * v + 1]),
                                fmaf((y[4 * v + 2] - mu) * r, lw[4 * v + 2], lb[4 * v + 2]),
                                fmaf((y[4 * v + 3] - mu) * r, lw[4 * v + 3], lb[4 * v + 3]));
        }
    }
}

// ---------------- K7: fused final GEMM + un-RevIN + transpose ----------------
// 321 blocks; block tile 64 rows x 96 cols; 128 threads; thread tile 8x6
__global__ void __launch_bounds__(128) k7_gemm(const float* __restrict__ rev_w,
                                               const float* __restrict__ rev_b,
                                               float* __restrict__ out) {
    __shared__ float As[2][16 * 68];
    __shared__ float Bs[2][16 * 96];
    int t = threadIdx.x;
    size_t bc0 = (size_t)blockIdx.x * 64;            // BC = 321*64
    int ty = t >> 4, tx = t & 15;                    // ty 0..7, tx 0..15
    int r0 = ty * 8, c0l = tx * 6;

    // loaders (128 threads)
    int lr = t >> 1, lk = (t & 1) * 8;               // As: row lr (0..63), 8 consecutive k
    int bk = t >> 3, bo = (t & 7) * 12;              // Bs: k-row bk (0..15), 12 floats

    uint32_t as_sm[2], bs_sm[2];
    as_sm[0] = (uint32_t)__cvta_generic_to_shared(&As[0][0]);
    as_sm[1] = (uint32_t)__cvta_generic_to_shared(&As[1][0]);
    bs_sm[0] = (uint32_t)__cvta_generic_to_shared(&Bs[0][0]);
    bs_sm[1] = (uint32_t)__cvta_generic_to_shared(&Bs[1][0]);

    float acc[8][6];
    #pragma unroll
    for (int i = 0; i < 8; i++)
        #pragma unroll
        for (int j = 0; j < 6; j++) acc[i][j] = 0.f;

    auto load_tile = [&](int it, int bu) {
        int k0 = it * 16;
        const float* srcrow;
        if (k0 < 1024) srcrow = g_y + (bc0 + lr) * 1024 + k0 + lk;
        else           srcrow = g_trend + (bc0 + lr) * 512 + (k0 - 1024) + lk;
        #pragma unroll
        for (int i = 0; i < 8; i++)
            cpa4(as_sm[bu] + (uint32_t)(((lk + i) * 68 + lr) * 4), srcrow + i);
        const float* bsrc = g_Wt + (k0 + bk) * 96 + bo;
        #pragma unroll
        for (int i = 0; i < 3; i++)
            cpa16(bs_sm[bu] + (uint32_t)((bk * 96 + bo + 4 * i) * 4), bsrc + 4 * i);
    };

    load_tile(0, 0);
    cp_commit();
    for (int it = 0; it < 96; it++) {
        int cur = it & 1;
        if (it + 1 < 96) {
            load_tile(it + 1, cur ^ 1);
            cp_commit();
            asm volatile("cp.async.wait_group 1;\n" ::: "memory");
        } else {
            asm volatile("cp.async.wait_group 0;\n" ::: "memory");
        }
        __syncthreads();
        #pragma unroll
        for (int k = 0; k < 16; k++) {
            float4 av0 = *(const float4*)&As[cur][k * 68 + r0];
            float4 av1 = *(const float4*)&As[cur][k * 68 + r0 + 4];
            float a8[8] = {av0.x, av0.y, av0.z, av0.w, av1.x, av1.y, av1.z, av1.w};
            const float* bp = &Bs[cur][k * 96 + c0l];
            float b6[6];
            #pragma unroll
            for (int j = 0; j < 6; j++) b6[j] = bp[j];
            #pragma unroll
            for (int i = 0; i < 8; i++)
                #pragma unroll
                for (int j = 0; j < 6; j++)
                    acc[i][j] = fmaf(a8[i], b6[j], acc[i][j]);
        }
        __syncthreads();
    }
    // epilogue: + cb, un-RevIN, transposed scatter
    #pragma unroll
    for (int i = 0; i < 8; i++) {
        size_t bc = bc0 + r0 + i;
        int b = (int)(bc / C_);
        int c = (int)(bc - (size_t)b * C_);
        float rw = rev_w[c], rb = rev_b[c];
        float sd = g_std[bc], mn = g_mean[bc];
        #pragma unroll
        for (int j = 0; j < 6; j++) {
            int col = c0l + j;
            float v = acc[i][j] + g_cb[col];
            v = fmaf((v - rb) / rw, sd, mn);
            out[((size_t)b * PRED_ + col) * C_ + c] = v;
        }
    }
}

// ---------------- launch ----------------
extern "C" void kernel_launch(void* const* d_in, const int* in_sizes, int n_in,
                              void* d_out, int out_size) {
    const float* x       = (const float*)d_in[0];
    const float* rev_w   = (const float*)d_in[1];
    const float* rev_b   = (const float*)d_in[2];
    const float* fc1_w   = (const float*)d_in[3];
    const float* fc1_b   = (const float*)d_in[4];
    const float* bn1_w   = (const float*)d_in[5];
    const float* bn1_b   = (const float*)d_in[6];
    const float* conv_w  = (const float*)d_in[7];
    const float* conv_b  = (const float*)d_in[8];
    const float* bn2_w   = (const float*)d_in[9];
    const float* bn2_b   = (const float*)d_in[10];
    const float* fc2_w   = (const float*)d_in[11];
    const float* fc2_b   = (const float*)d_in[12];
    const float* m1_w    = (const float*)d_in[13];
    const float* m1_b    = (const float*)d_in[14];
    const float* m2_w    = (const float*)d_in[15];
    const float* m2_b    = (const float*)d_in[16];
    const float* gl_sc   = (const float*)d_in[17];
    const float* ln_w    = (const float*)d_in[18];
    const float* ln_b    = (const float*)d_in[19];
    const float* seas_w  = (const float*)d_in[20];
    const float* seas_b  = (const float*)d_in[21];
    const float* tr_w    = (const float*)d_in[22];
    const float* tr_b    = (const float*)d_in[23];
    const float* fus_w   = (const float*)d_in[24];
    const float* fus_b   = (const float*)d_in[25];
    float* out = (float*)d_out;

    const int K1_SMEM = 512 * 33 * 2 * sizeof(float);   // 135168
    const int KG_SMEM = 19584 * sizeof(float);           // 78336
    cudaFuncSetAttribute(k1_prep, cudaFuncAttributeMaxDynamicSharedMemorySize, K1_SMEM);
    cudaFuncSetAttribute(kg_gate, cudaFuncAttributeMaxDynamicSharedMemorySize, KG_SMEM);

    k0_fold1<<<384, 256>>>(seas_w, fus_w);
    k0_fold2<<<192, 256>>>(tr_w, fus_w);
    k0_cb<<<1, 96>>>(fus_w, fus_b, seas_b, tr_b);
    k1_prep<<<dim3(11, 64), 256, K1_SMEM>>>(x, rev_w, rev_b, fc1_w, fc1_b);   // launch #4 -> profiled
    k3_stats1<<<1, 1024>>>(bn1_w, bn1_b);
    k4_conv<<<NB1, 256>>>(conv_w, conv_b);
    k5_stats2<<<1, 1024>>>(bn2_w, bn2_b);
    kg_gate<<<642, 256, KG_SMEM>>>(m1_w, m1_b, m2_w, m2_b);
    k6_local<<<NB1, 256>>>(conv_w, conv_b, fc2_w, fc2_b, gl_sc, ln_w, ln_b);
    k7_gemm<<<321, 128>>>(rev_w, rev_b, out);
    (void)in_sizes; (void)n_in; (void)out_size;
}

// round 10
// speedup vs baseline: 2.2541x; 1.1342x over previous
#include <cuda_runtime.h>
#include <cuda_bf16.h>
#include <math.h>
#include <stdint.h>
#include <stddef.h>

#define B_ 64
#define L_ 512
#define C_ 321
#define BC 20544            // B_*C_
#define PRED_ 96
#define LP 520              // L + STRIDE
#define NB1 1284            // BC/16 blocks (k1b/k4/k6)
#define CNT_BN 657408.0f    // BC*32
#define EPS_ 1e-5f

// ---------------- scratch (__device__ globals; no runtime allocation) ----------------
static __device__ float g_s[(size_t)BC * LP];        // seasonal, padded
static __device__ float g_trend[(size_t)BC * L_];    // trend rows [bc][L]
static __device__ float g_mean[BC];
static __device__ float g_std[BC];
static __device__ float g_h[(size_t)BC * 2048];      // h1 = gelu(fc1), layout [bc][j(32)][n(64)]
static __device__ float g_y[(size_t)BC * 1024];      // post-LN y [bc][1024]
static __device__ float g_pool[(size_t)BC * 64];     // sp.mean(-1)
static __device__ float g_w[(size_t)BC * 64];        // gating sigmoid output
static __device__ float g_Wt[1536 * 96];             // folded weights, [k][j]
static __device__ float g_cb[96];                    // folded bias
static __device__ float g_p1s[NB1 * 64];
static __device__ float g_p1q[NB1 * 64];
static __device__ float g_p2s[NB1 * 64];
static __device__ float g_p2q[NB1 * 64];
static __device__ float g_sc1[64], g_bi1[64], g_sc2[64], g_bi2[64];

__device__ __forceinline__ float geluf(float v) {
    return 0.5f * v * (1.0f + erff(v * 0.70710678f));
}
__device__ __forceinline__ float sigf(float v) {
    return 1.0f / (1.0f + expf(-v));
}

// cp.async helpers (LDGSTS)
__device__ __forceinline__ void cpa4(uint32_t d, const float* s) {
    asm volatile("cp.async.ca.shared.global [%0], [%1], 4;\n" :: "r"(d), "l"(s));
}
__device__ __forceinline__ void cpa16(uint32_t d, const float* s) {
    asm volatile("cp.async.ca.shared.global [%0], [%1], 16;\n" :: "r"(d), "l"(s));
}
__device__ __forceinline__ void cp_commit() {
    asm volatile("cp.async.commit_group;\n" ::: "memory");
}

// ---------------- K0: fold fusion layer ----------------
__global__ void k0_fold1(const float* __restrict__ seas_w, const float* __restrict__ fus_w) {
    int idx = blockIdx.x * 256 + threadIdx.x;       // 96*1024
    int j = idx >> 10, m = idx & 1023;
    const float* fw = fus_w + j * 192;
    float a = 0.f;
    #pragma unroll 8
    for (int k = 0; k < 96; k++) a = fmaf(fw[k], seas_w[k * 1024 + m], a);
    g_Wt[m * 96 + j] = a;
}
__global__ void k0_fold2(const float* __restrict__ tr_w, const float* __restrict__ fus_w) {
    int idx = blockIdx.x * 256 + threadIdx.x;       // 96*512
    int j = idx >> 9, m = idx & 511;
    const float* fw = fus_w + j * 192 + 96;
    float a = 0.f;
    #pragma unroll 8
    for (int k = 0; k < 96; k++) a = fmaf(fw[k], tr_w[k * 512 + m], a);
    g_Wt[(1024 + m) * 96 + j] = a;
}
__global__ void k0_cb(const float* __restrict__ fus_w, const float* __restrict__ fus_b,
                      const float* __restrict__ seas_b, const float* __restrict__ tr_b) {
    int j = threadIdx.x;
    float a = fus_b[j];
    for (int k = 0; k < 96; k++) {
        a = fmaf(fus_w[j * 192 + k], seas_b[k], a);
        a = fmaf(fus_w[j * 192 + 96 + k], tr_b[k], a);
    }
    g_cb[j] = a;
}

// ---------------- K1a: RevIN stats + segmented EMA + seasonal/trend + pooled ----------------
__global__ void __launch_bounds__(256) k1a_prep(const float* __restrict__ x,
                                                const float* __restrict__ rev_w,
                                                const float* __restrict__ rev_b) {
    extern __shared__ float sm[];
    float* xb = sm;                 // [512][33]
    float* tb = sm + 512 * 33;      // [512][33]
    __shared__ float red_s[8][33], red_q[8][33], meanb[32], stdb[32];
    __shared__ float segend[8][33], carry[8][33];
    __shared__ float pw[65];
    int b = blockIdx.y;
    int c0 = blockIdx.x * 32;
    int t = threadIdx.x;
    int w = t >> 5, lane = t & 31;
    int c = c0 + lane;
    bool cv = (c < C_);

    if (t == 0) {
        pw[0] = 1.f;
        for (int j = 1; j <= 64; j++) pw[j] = pw[j - 1] * 0.8f;
    }

    float s = 0.f, q = 0.f;
    for (int l = w; l < L_; l += 8) {
        float v = cv ? x[((size_t)b * L_ + l) * C_ + c] : 0.f;
        xb[l * 33 + lane] = v;
        s += v;
        q = fmaf(v, v, q);
    }
    red_s[w][lane] = s; red_q[w][lane] = q;
    __syncthreads();
    if (w == 0) {
        float ss = 0.f, qq = 0.f;
        #pragma unroll
        for (int i = 0; i < 8; i++) { ss += red_s[i][lane]; qq += red_q[i][lane]; }
        float mu = ss * (1.f / (float)L_);
        float v2 = fmaxf(qq - (float)L_ * mu * mu, 0.f);
        float sd = sqrtf(v2 * (1.f / (float)(L_ - 1))) + EPS_;
        meanb[lane] = mu; stdb[lane] = sd;
        if (cv) { int bc = b * C_ + c; g_mean[bc] = mu; g_std[bc] = sd; }
    }
    __syncthreads();
    {
        float rw = cv ? rev_w[c] : 1.f;
        float rb = cv ? rev_b[c] : 0.f;
        float mu = meanb[lane], inv = 1.f / stdb[lane];
        for (int l = w; l < L_; l += 8) {
            float v = xb[l * 33 + lane];
            xb[l * 33 + lane] = fmaf((v - mu) * inv, rw, rb);
        }
    }
    __syncthreads();
    {
        int base = w * 64;
        float cl;
        if (w == 0) {
            cl = xb[lane];
            tb[lane] = cl;
            #pragma unroll 4
            for (int l = 1; l < 64; l++) {
                cl = fmaf(0.8f, cl, 0.2f * xb[l * 33 + lane]);
                tb[l * 33 + lane] = cl;
            }
        } else {
            cl = 0.f;
            #pragma unroll 4
            for (int j = 0; j < 64; j++) {
                int l = base + j;
                cl = fmaf(0.8f, cl, 0.2f * xb[l * 33 + lane]);
                tb[l * 33 + lane] = cl;
            }
        }
        segend[w][lane] = cl;
    }
    __syncthreads();
    if (t < 32) {
        float cacc = segend[0][t];
        carry[1][t] = cacc;
        float q64 = pw[64];
        #pragma unroll
        for (int s2 = 1; s2 <= 6; s2++) {
            cacc = fmaf(q64, cacc, segend[s2][t]);
            carry[s2 + 1][t] = cacc;
        }
    }
    __syncthreads();
    {
        int base = w * 64;
        float cin = (w == 0) ? 0.f : carry[w][lane];
        #pragma unroll 4
        for (int j = 0; j < 64; j++) {
            int l = base + j;
            float tf = fmaf(pw[j + 1], cin, tb[l * 33 + lane]);
            tb[l * 33 + lane] = tf;
            xb[l * 33 + lane] = xb[l * 33 + lane] - tf;
        }
    }
    __syncthreads();
    for (int ci = w; ci < 32; ci += 8) {
        int cc = c0 + ci;
        if (cc >= C_) continue;
        size_t bc = (size_t)b * C_ + cc;
        float* gs = g_s + bc * LP;
        float* gt = g_trend + bc * (size_t)L_;
        for (int l0 = 0; l0 < L_; l0 += 32) {
            gs[l0 + lane] = xb[(l0 + lane) * 33 + ci];
            gt[l0 + lane] = tb[(l0 + lane) * 33 + ci];
        }
        if (lane < 8) gs[L_ + lane] = xb[511 * 33 + ci];
        #pragma unroll
        for (int nn = 0; nn < 2; nn++) {
            int n = 2 * lane + nn;
            float sum = 0.f;
            #pragma unroll
            for (int p = 0; p < 16; p++) {
                int l = n * 8 + p;
                if (l > 511) l = 511;
                sum += xb[l * 33 + ci];
            }
            g_pool[bc * 64 + n] = sum * (1.f / 16.f);
        }
    }
}

// ---------------- K1b: fc1 + gelu -> g_h ([bc][j][n]); bn1 per-n partials ----------------
// 1284 blocks x 256 threads; lane = j (0..31), warp = n-slice; broadcast seasonal reads.
__global__ void __launch_bounds__(256) k1b_fc1(const float* __restrict__ fc1_w,
                                               const float* __restrict__ fc1_b) {
    __shared__ float s_sm[16 * LP];       // 33280B
    __shared__ float wt[512];             // wt[p*32+j] = fc1_w[j*16+p]
    __shared__ float stage[32 * 65];      // [j][n] padded
    int t = threadIdx.x;
    int w = t >> 5, lane = t & 31;
    size_t bc0 = (size_t)blockIdx.x * 16;
    for (int i = t; i < 512; i += 256) {
        int p = i >> 5, j = i & 31;
        wt[i] = fc1_w[j * 16 + p];
    }
    for (int i = t; i < 16 * LP; i += 256) s_sm[i] = g_s[bc0 * LP + i];
    __syncthreads();
    float wj[16];
    #pragma unroll
    for (int p = 0; p < 16; p++) wj[p] = wt[p * 32 + lane];
    float bj = fc1_b[lane];
    float ps[8], pq[8];
    #pragma unroll
    for (int i = 0; i < 8; i++) { ps[i] = 0.f; pq[i] = 0.f; }

    for (int r = 0; r < 16; r++) {
        const float* sp = s_sm + r * LP;
        #pragma unroll
        for (int nn = 0; nn < 8; nn++) {
            int n = nn * 8 + w;
            const float* pp = sp + n * 8;            // n*8+15 <= 519 < LP (padded)
            float acc = bj;
            #pragma unroll
            for (int p = 0; p < 16; p++) acc = fmaf(pp[p], wj[p], acc);
            float g = geluf(acc);
            ps[nn] += g;
            pq[nn] = fmaf(g, g, pq[nn]);
            stage[lane * 65 + n] = g;
        }
        __syncthreads();
        float* dst = g_h + (bc0 + r) * 2048;
        for (int i = t; i < 2048; i += 256)
            dst[i] = stage[(i >> 6) * 65 + (i & 63)];
        __syncthreads();
    }
    // warp-reduce per-n partials across j lanes
    #pragma unroll
    for (int nn = 0; nn < 8; nn++) {
        float s = ps[nn], q = pq[nn];
        #pragma unroll
        for (int off = 16; off; off >>= 1) {
            s += __shfl_down_sync(0xffffffff, s, off);
            q += __shfl_down_sync(0xffffffff, q, off);
        }
        if (lane == 0) {
            int n = nn * 8 + w;
            g_p1s[blockIdx.x * 64 + n] = s;
            g_p1q[blockIdx.x * 64 + n] = q;
        }
    }
}

// ---------------- K3/K5: reduce bn partials ----------------
__global__ void __launch_bounds__(1024) k3_stats1(const float* __restrict__ bn_w,
                                                  const float* __restrict__ bn_b) {
    __shared__ float ss[1024], qq[1024];
    int t = threadIdx.x;
    int n = t & 63, part = t >> 6;
    float s = 0.f, q = 0.f;
    for (int blk = part; blk < NB1; blk += 16) { s += g_p1s[blk * 64 + n]; q += g_p1q[blk * 64 + n]; }
    ss[t] = s; qq[t] = q;
    __syncthreads();
    if (t < 64) {
        float S = 0.f, Q = 0.f;
        #pragma unroll
        for (int i = 0; i < 16; i++) { S += ss[t + 64 * i]; Q += qq[t + 64 * i]; }
        float inv = 1.f / CNT_BN;
        float mu = S * inv;
        float var = fmaxf(Q * inv - mu * mu, 0.f);
        float sc = bn_w[t] * rsqrtf(var + EPS_);
        g_sc1[t] = sc;
        g_bi1[t] = fmaf(-mu, sc, bn_b[t]);
    }
}
__global__ void __launch_bounds__(1024) k5_stats2(const float* __restrict__ bn_w,
                                                  const float* __restrict__ bn_b) {
    __shared__ float ss[1024], qq[1024];
    int t = threadIdx.x;
    int n = t & 63, part = t >> 6;
    float s = 0.f, q = 0.f;
    for (int blk = part; blk < NB1; blk += 16) { s += g_p2s[blk * 64 + n]; q += g_p2q[blk * 64 + n]; }
    ss[t] = s; qq[t] = q;
    __syncthreads();
    if (t < 64) {
        float S = 0.f, Q = 0.f;
        #pragma unroll
        for (int i = 0; i < 16; i++) { S += ss[t + 64 * i]; Q += qq[t + 64 * i]; }
        float inv = 1.f / CNT_BN;
        float mu = S * inv;
        float var = fmaxf(Q * inv - mu * mu, 0.f);
        float sc = bn_w[t] * rsqrtf(var + EPS_);
        g_sc2[t] = sc;
        g_bi2[t] = fmaf(-mu, sc, bn_b[t]);
    }
}

// ---------------- K4: read g_h, bn1 affine + conv3 + gelu; bn2 partials ----------------
__global__ void __launch_bounds__(256) k4_conv(const float* __restrict__ conv_w,
                                               const float* __restrict__ conv_b) {
    __shared__ float rs[256], rq[256];
    int t = threadIdx.x;
    size_t bc0 = (size_t)blockIdx.x * 16;
    int n = t & 63;
    float sc = g_sc1[n], bi = g_bi1[n];
    float c0 = conv_w[n * 3], c1 = conv_w[n * 3 + 1], c2 = conv_w[n * 3 + 2];
    float cbv = conv_b[n];
    float psum = 0.f, psq = 0.f;
    #pragma unroll
    for (int q = 0; q < 4; q++) {
        int pair = t + 256 * q;
        int row = pair >> 6;
        const float* hp = g_h + (bc0 + row) * 2048 + n;
        float a[34];
        a[0] = 0.f; a[33] = 0.f;
        #pragma unroll
        for (int j = 0; j < 32; j++) a[j + 1] = fmaf(hp[j * 64], sc, bi);
        #pragma unroll
        for (int j = 0; j < 32; j++) {
            float vv = cbv;
            vv = fmaf(a[j], c0, vv);
            vv = fmaf(a[j + 1], c1, vv);
            vv = fmaf(a[j + 2], c2, vv);
            float g = geluf(vv);
            psum += g;
            psq = fmaf(g, g, psq);
        }
    }
    rs[t] = psum; rq[t] = psq;
    __syncthreads();
    if (t < 64) {
        float S = rs[t] + rs[t + 64] + rs[t + 128] + rs[t + 192];
        float Q = rq[t] + rq[t + 64] + rq[t + 128] + rq[t + 192];
        g_p2s[blockIdx.x * 64 + t] = S;
        g_p2q[blockIdx.x * 64 + t] = Q;
    }
}

// ---------------- Kg: gating MLP, warp-per-row, 32 rows/block ----------------
__global__ void __launch_bounds__(256) kg_gate(const float* __restrict__ m1_w,
                                               const float* __restrict__ m1_b,
                                               const float* __restrict__ m2_w,
                                               const float* __restrict__ m2_b) {
    extern __shared__ float kg_sm[];
    float* m1p = kg_sm;                 // 8320
    float* m2t = kg_sm + 8320;          // 8192
    float* ps  = kg_sm + 16512;         // 2048
    float* us  = kg_sm + 18560;         // 1024
    int t = threadIdx.x;
    int w = t >> 5, lane = t & 31;
    size_t bc0 = (size_t)blockIdx.x * 32;
    for (int i = t; i < 8192; i += 256) {
        int h = i >> 6, k = i & 63;
        m1p[h * 65 + k] = m1_w[i];
    }
    for (int i = t; i < 8192; i += 256) {
        int nn = i >> 7, h = i & 127;
        m2t[h * 64 + nn] = m2_w[i];
    }
    for (int i = t; i < 2048; i += 256)
        ps[i] = g_pool[bc0 * 64 + i];
    __syncthreads();
    float* uw = us + w * 128;
    #pragma unroll
    for (int rr = 0; rr < 4; rr++) {
        int rloc = rr * 8 + w;
        const float* pr = ps + rloc * 64;
        float u0 = m1_b[lane], u1 = m1_b[lane + 32], u2 = m1_b[lane + 64], u3 = m1_b[lane + 96];
        #pragma unroll 8
        for (int k = 0; k < 64; k++) {
            float pk = pr[k];
            u0 = fmaf(pk, m1p[lane * 65 + k], u0);
            u1 = fmaf(pk, m1p[(lane + 32) * 65 + k], u1);
            u2 = fmaf(pk, m1p[(lane + 64) * 65 + k], u2);
            u3 = fmaf(pk, m1p[(lane + 96) * 65 + k], u3);
        }
        uw[lane] = geluf(u0);
        uw[lane + 32] = geluf(u1);
        uw[lane + 64] = geluf(u2);
        uw[lane + 96] = geluf(u3);
        __syncwarp();
        float a0 = m2_b[lane], a1 = m2_b[lane + 32];
        #pragma unroll 8
        for (int h = 0; h < 128; h++) {
            float uh = uw[h];
            a0 = fmaf(uh, m2t[h * 64 + lane], a0);
            a1 = fmaf(uh, m2t[h * 64 + lane + 32], a1);
        }
        g_w[(bc0 + rloc) * 64 + lane] = sigf(a0);
        g_w[(bc0 + rloc) * 64 + lane + 32] = sigf(a1);
        __syncwarp();
    }
}

// ---------------- K6: read g_h, chain conv/bn2/fc2 + combine + LN -> g_y ----------------
__global__ void __launch_bounds__(256) k6_local(const float* __restrict__ conv_w,
                                                const float* __restrict__ conv_b,
                                                const float* __restrict__ fc2_w,
                                                const float* __restrict__ fc2_b,
                                                const float* __restrict__ gl_scale,
                                                const float* __restrict__ ln_w,
                                                const float* __restrict__ ln_b) {
    __shared__ float s_sm[16 * LP];
    __shared__ float w2[512], b2[16], lw[16], lb[16];
    int t = threadIdx.x;
    size_t bc0 = (size_t)blockIdx.x * 16;
    w2[t] = fc2_w[t];
    w2[t + 256] = fc2_w[t + 256];
    if (t < 16) { b2[t] = fc2_b[t]; lw[t] = ln_w[t]; lb[t] = ln_b[t]; }
    for (int i = t; i < 16 * LP; i += 256) s_sm[i] = g_s[bc0 * LP + i];
    __syncthreads();
    float gs = gl_scale[0];
    int n = t & 63;
    float sc1v = g_sc1[n], bi1v = g_bi1[n];
    float sc2v = g_sc2[n], bi2v = g_bi2[n];
    float c0 = conv_w[n * 3], c1 = conv_w[n * 3 + 1], c2 = conv_w[n * 3 + 2];
    float cbv = conv_b[n];
    #pragma unroll
    for (int q = 0; q < 4; q++) {
        int pair = t + 256 * q;
        int row = pair >> 6;
        size_t bc = bc0 + row;
        const float* hp = g_h + bc * 2048 + n;
        float a[34];
        a[0] = 0.f; a[33] = 0.f;
        #pragma unroll
        for (int j = 0; j < 32; j++) a[j + 1] = fmaf(hp[j * 64], sc1v, bi1v);
        float left = 0.f;
        #pragma unroll
        for (int j = 0; j < 32; j++) {
            float cur = a[j + 1];
            float vv = cbv;
            vv = fmaf(left, c0, vv);
            vv = fmaf(cur, c1, vv);
            vv = fmaf(a[j + 2], c2, vv);
            left = cur;
            a[j + 1] = fmaf(geluf(vv), sc2v, bi2v);
        }
        float p[16];
        const float4* spp = (const float4*)(s_sm + row * LP + n * 8);
        #pragma unroll
        for (int v = 0; v < 4; v++) {
            float4 f = spp[v];
            p[4 * v] = f.x; p[4 * v + 1] = f.y; p[4 * v + 2] = f.z; p[4 * v + 3] = f.w;
        }
        float wv = g_w[bc * 64 + n];
        float m3 = fmaf(gs, wv, 3.f);
        float y[16];
        float musum = 0.f;
        #pragma unroll
        for (int pp = 0; pp < 16; pp++) {
            float acc = b2[pp];
            const float4* wp = (const float4*)(w2 + pp * 32);
            #pragma unroll
            for (int j = 0; j < 8; j++) {
                float4 f = wp[j];
                acc = fmaf(a[4 * j + 1], f.x, acc);
                acc = fmaf(a[4 * j + 2], f.y, acc);
                acc = fmaf(a[4 * j + 3], f.z, acc);
                acc = fmaf(a[4 * j + 4], f.w, acc);
            }
            float yy = fmaf(p[pp], m3, acc);
            y[pp] = yy;
            musum += yy;
        }
        float mu = musum * (1.f / 16.f);
        float s2 = 0.f;
        #pragma unroll
        for (int pp = 0; pp < 16; pp++) { float d = y[pp] - mu; s2 = fmaf(d, d, s2); }
        float r = rsqrtf(s2 * (1.f / 16.f) + EPS_);
        float4* gy = (float4*)(g_y + bc * 1024 + (size_t)n * 16);
        #pragma unroll
        for (int v = 0; v < 4; v++) {
            gy[v] = make_float4(fmaf((y[4 * v] - mu) * r, lw[4 * v], lb[4 * v]),
                                fmaf((y[4 * v + 1] - mu) * r, lw[4 * v + 1], lb[4 * v + 1]),
                                fmaf((y[4 * v + 2] - mu) * r, lw[4 * v + 2], lb[4 * v + 2]),
                                fmaf((y[4 * v + 3] - mu) * r, lw[4 * v + 3], lb[4 * v + 3]));
        }
    }
}

// ---------------- K7: fused final GEMM + un-RevIN + transpose ----------------
__global__ void __launch_bounds__(128) k7_gemm(const float* __restrict__ rev_w,
                                               const float* __restrict__ rev_b,
                                               float* __restrict__ out) {
    __shared__ float As[2][16 * 68];
    __shared__ float Bs[2][16 * 96];
    int t = threadIdx.x;
    size_t bc0 = (size_t)blockIdx.x * 64;
    int ty = t >> 4, tx = t & 15;
    int r0 = ty * 8, c0l = tx * 6;

    int lr = t >> 1, lk = (t & 1) * 8;
    int bk = t >> 3, bo = (t & 7) * 12;

    uint32_t as_sm[2], bs_sm[2];
    as_sm[0] = (uint32_t)__cvta_generic_to_shared(&As[0][0]);
    as_sm[1] = (uint32_t)__cvta_generic_to_shared(&As[1][0]);
    bs_sm[0] = (uint32_t)__cvta_generic_to_shared(&Bs[0][0]);
    bs_sm[1] = (uint32_t)__cvta_generic_to_shared(&Bs[1][0]);

    float acc[8][6];
    #pragma unroll
    for (int i = 0; i < 8; i++)
        #pragma unroll
        for (int j = 0; j < 6; j++) acc[i][j] = 0.f;

    auto load_tile = [&](int it, int bu) {
        int k0 = it * 16;
        const float* srcrow;
        if (k0 < 1024) srcrow = g_y + (bc0 + lr) * 1024 + k0 + lk;
        else           srcrow = g_trend + (bc0 + lr) * 512 + (k0 - 1024) + lk;
        #pragma unroll
        for (int i = 0; i < 8; i++)
            cpa4(as_sm[bu] + (uint32_t)(((lk + i) * 68 + lr) * 4), srcrow + i);
        const float* bsrc = g_Wt + (k0 + bk) * 96 + bo;
        #pragma unroll
        for (int i = 0; i < 3; i++)
            cpa16(bs_sm[bu] + (uint32_t)((bk * 96 + bo + 4 * i) * 4), bsrc + 4 * i);
    };

    load_tile(0, 0);
    cp_commit();
    for (int it = 0; it < 96; it++) {
        int cur = it & 1;
        if (it + 1 < 96) {
            load_tile(it + 1, cur ^ 1);
            cp_commit();
            asm volatile("cp.async.wait_group 1;\n" ::: "memory");
        } else {
            asm volatile("cp.async.wait_group 0;\n" ::: "memory");
        }
        __syncthreads();
        #pragma unroll
        for (int k = 0; k < 16; k++) {
            float4 av0 = *(const float4*)&As[cur][k * 68 + r0];
            float4 av1 = *(const float4*)&As[cur][k * 68 + r0 + 4];
            float a8[8] = {av0.x, av0.y, av0.z, av0.w, av1.x, av1.y, av1.z, av1.w};
            const float* bp = &Bs[cur][k * 96 + c0l];
            float b6[6];
            #pragma unroll
            for (int j = 0; j < 6; j++) b6[j] = bp[j];
            #pragma unroll
            for (int i = 0; i < 8; i++)
                #pragma unroll
                for (int j = 0; j < 6; j++)
                    acc[i][j] = fmaf(a8[i], b6[j], acc[i][j]);
        }
        __syncthreads();
    }
    #pragma unroll
    for (int i = 0; i < 8; i++) {
        size_t bc = bc0 + r0 + i;
        int b = (int)(bc / C_);
        int c = (int)(bc - (size_t)b * C_);
        float rw = rev_w[c], rb = rev_b[c];
        float sd = g_std[bc], mn = g_mean[bc];
        #pragma unroll
        for (int j = 0; j < 6; j++) {
            int col = c0l + j;
            float v = acc[i][j] + g_cb[col];
            v = fmaf((v - rb) / rw, sd, mn);
            out[((size_t)b * PRED_ + col) * C_ + c] = v;
        }
    }
}

// ---------------- launch ----------------
extern "C" void kernel_launch(void* const* d_in, const int* in_sizes, int n_in,
                              void* d_out, int out_size) {
    const float* x       = (const float*)d_in[0];
    const float* rev_w   = (const float*)d_in[1];
    const float* rev_b   = (const float*)d_in[2];
    const float* fc1_w   = (const float*)d_in[3];
    const float* fc1_b   = (const float*)d_in[4];
    const float* bn1_w   = (const float*)d_in[5];
    const float* bn1_b   = (const float*)d_in[6];
    const float* conv_w  = (const float*)d_in[7];
    const float* conv_b  = (const float*)d_in[8];
    const float* bn2_w   = (const float*)d_in[9];
    const float* bn2_b   = (const float*)d_in[10];
    const float* fc2_w   = (const float*)d_in[11];
    const float* fc2_b   = (const float*)d_in[12];
    const float* m1_w    = (const float*)d_in[13];
    const float* m1_b    = (const float*)d_in[14];
    const float* m2_w    = (const float*)d_in[15];
    const float* m2_b    = (const float*)d_in[16];
    const float* gl_sc   = (const float*)d_in[17];
    const float* ln_w    = (const float*)d_in[18];
    const float* ln_b    = (const float*)d_in[19];
    const float* seas_w  = (const float*)d_in[20];
    const float* seas_b  = (const float*)d_in[21];
    const float* tr_w    = (const float*)d_in[22];
    const float* tr_b    = (const float*)d_in[23];
    const float* fus_w   = (const float*)d_in[24];
    const float* fus_b   = (const float*)d_in[25];
    float* out = (float*)d_out;

    const int K1_SMEM = 512 * 33 * 2 * sizeof(float);   // 135168
    const int KG_SMEM = 19584 * sizeof(float);           // 78336
    cudaFuncSetAttribute(k1a_prep, cudaFuncAttributeMaxDynamicSharedMemorySize, K1_SMEM);
    cudaFuncSetAttribute(kg_gate, cudaFuncAttributeMaxDynamicSharedMemorySize, KG_SMEM);

    k1a_prep<<<dim3(11, 64), 256, K1_SMEM>>>(x, rev_w, rev_b);   // launch 1
    k1b_fc1<<<NB1, 256>>>(fc1_w, fc1_b);                          // launch 2
    k3_stats1<<<1, 1024>>>(bn1_w, bn1_b);                         // launch 3
    k4_conv<<<NB1, 256>>>(conv_w, conv_b);                        // launch 4 -> profiled
    k5_stats2<<<1, 1024>>>(bn2_w, bn2_b);
    kg_gate<<<642, 256, KG_SMEM>>>(m1_w, m1_b, m2_w, m2_b);
    k6_local<<<NB1, 256>>>(conv_w, conv_b, fc2_w, fc2_b, gl_sc, ln_w, ln_b);
    k0_fold1<<<384, 256>>>(seas_w, fus_w);
    k0_fold2<<<192, 256>>>(tr_w, fus_w);
    k0_cb<<<1, 96>>>(fus_w, fus_b, seas_b, tr_b);
    k7_gemm<<<321, 128>>>(rev_w, rev_b, out);
    (void)in_sizes; (void)n_in; (void)out_size;
}

// round 11
// speedup vs baseline: 3.7700x; 1.6725x over previous
#include <cuda_runtime.h>
#include <cuda_bf16.h>
#include <math.h>
#include <stdint.h>
#include <stddef.h>

#define B_ 64
#define L_ 512
#define C_ 321
#define BC 20544            // B_*C_
#define PRED_ 96
#define LP 520              // L + STRIDE
#define NB1 1284            // BC/16 blocks (k1b/k4/k6)
#define CNT_BN 657408.0f    // BC*32
#define EPS_ 1e-5f

// ---------------- scratch (__device__ globals; no runtime allocation) ----------------
static __device__ float g_s[(size_t)BC * LP];        // seasonal, padded
static __device__ float g_trend[(size_t)BC * L_];    // trend rows [bc][L]
static __device__ float g_mean[BC];
static __device__ float g_std[BC];
static __device__ float g_h[(size_t)BC * 2048];      // h1 = gelu(fc1), layout [bc][j(32)][n(64)]
static __device__ float g_y[(size_t)BC * 1024];      // post-LN y [bc][1024]
static __device__ float g_pool[(size_t)BC * 64];     // sp.mean(-1)
static __device__ float g_w[(size_t)BC * 64];        // gating sigmoid output
static __device__ float g_Wt[1536 * 96];             // folded weights, [k][j]
static __device__ float g_cb[96];                    // folded bias
static __device__ float g_p1s[NB1 * 64];
static __device__ float g_p1q[NB1 * 64];
static __device__ float g_p2s[NB1 * 64];
static __device__ float g_p2q[NB1 * 64];
static __device__ float g_sc1[64], g_bi1[64], g_sc2[64], g_bi2[64];

__device__ __forceinline__ float geluf(float v) {
    return 0.5f * v * (1.0f + erff(v * 0.70710678f));
}
__device__ __forceinline__ float sigf(float v) {
    return 1.0f / (1.0f + expf(-v));
}

// cp.async helpers (LDGSTS)
__device__ __forceinline__ void cpa16(uint32_t d, const float* s) {
    asm volatile("cp.async.ca.shared.global [%0], [%1], 16;\n" :: "r"(d), "l"(s));
}
__device__ __forceinline__ void cp_commit() {
    asm volatile("cp.async.commit_group;\n" ::: "memory");
}

// ---------------- K0: fold fusion layer ----------------
__global__ void k0_fold1(const float* __restrict__ seas_w, const float* __restrict__ fus_w) {
    int idx = blockIdx.x * 256 + threadIdx.x;       // 96*1024
    int j = idx >> 10, m = idx & 1023;
    const float* fw = fus_w + j * 192;
    float a = 0.f;
    #pragma unroll 8
    for (int k = 0; k < 96; k++) a = fmaf(fw[k], seas_w[k * 1024 + m], a);
    g_Wt[m * 96 + j] = a;
}
__global__ void k0_fold2(const float* __restrict__ tr_w, const float* __restrict__ fus_w) {
    int idx = blockIdx.x * 256 + threadIdx.x;       // 96*512
    int j = idx >> 9, m = idx & 511;
    const float* fw = fus_w + j * 192 + 96;
    float a = 0.f;
    #pragma unroll 8
    for (int k = 0; k < 96; k++) a = fmaf(fw[k], tr_w[k * 512 + m], a);
    g_Wt[(1024 + m) * 96 + j] = a;
}
__global__ void k0_cb(const float* __restrict__ fus_w, const float* __restrict__ fus_b,
                      const float* __restrict__ seas_b, const float* __restrict__ tr_b) {
    int j = threadIdx.x;
    float a = fus_b[j];
    for (int k = 0; k < 96; k++) {
        a = fmaf(fus_w[j * 192 + k], seas_b[k], a);
        a = fmaf(fus_w[j * 192 + 96 + k], tr_b[k], a);
    }
    g_cb[j] = a;
}

// ---------------- K1a: RevIN stats + segmented EMA + seasonal/trend + pooled ----------------
__global__ void __launch_bounds__(256) k1a_prep(const float* __restrict__ x,
                                                const float* __restrict__ rev_w,
                                                const float* __restrict__ rev_b) {
    extern __shared__ float sm[];
    float* xb = sm;                 // [512][33]
    float* tb = sm + 512 * 33;      // [512][33]
    __shared__ float red_s[8][33], red_q[8][33], meanb[32], stdb[32];
    __shared__ float segend[8][33], carry[8][33];
    __shared__ float pw[65];
    int b = blockIdx.y;
    int c0 = blockIdx.x * 32;
    int t = threadIdx.x;
    int w = t >> 5, lane = t & 31;
    int c = c0 + lane;
    bool cv = (c < C_);

    if (t == 0) {
        pw[0] = 1.f;
        for (int j = 1; j <= 64; j++) pw[j] = pw[j - 1] * 0.8f;
    }

    float s = 0.f, q = 0.f;
    for (int l = w; l < L_; l += 8) {
        float v = cv ? x[((size_t)b * L_ + l) * C_ + c] : 0.f;
        xb[l * 33 + lane] = v;
        s += v;
        q = fmaf(v, v, q);
    }
    red_s[w][lane] = s; red_q[w][lane] = q;
    __syncthreads();
    if (w == 0) {
        float ss = 0.f, qq = 0.f;
        #pragma unroll
        for (int i = 0; i < 8; i++) { ss += red_s[i][lane]; qq += red_q[i][lane]; }
        float mu = ss * (1.f / (float)L_);
        float v2 = fmaxf(qq - (float)L_ * mu * mu, 0.f);
        float sd = sqrtf(v2 * (1.f / (float)(L_ - 1))) + EPS_;
        meanb[lane] = mu; stdb[lane] = sd;
        if (cv) { int bc = b * C_ + c; g_mean[bc] = mu; g_std[bc] = sd; }
    }
    __syncthreads();
    {
        float rw = cv ? rev_w[c] : 1.f;
        float rb = cv ? rev_b[c] : 0.f;
        float mu = meanb[lane], inv = 1.f / stdb[lane];
        for (int l = w; l < L_; l += 8) {
            float v = xb[l * 33 + lane];
            xb[l * 33 + lane] = fmaf((v - mu) * inv, rw, rb);
        }
    }
    __syncthreads();
    {
        int base = w * 64;
        float cl;
        if (w == 0) {
            cl = xb[lane];
            tb[lane] = cl;
            #pragma unroll 4
            for (int l = 1; l < 64; l++) {
                cl = fmaf(0.8f, cl, 0.2f * xb[l * 33 + lane]);
                tb[l * 33 + lane] = cl;
            }
        } else {
            cl = 0.f;
            #pragma unroll 4
            for (int j = 0; j < 64; j++) {
                int l = base + j;
                cl = fmaf(0.8f, cl, 0.2f * xb[l * 33 + lane]);
                tb[l * 33 + lane] = cl;
            }
        }
        segend[w][lane] = cl;
    }
    __syncthreads();
    if (t < 32) {
        float cacc = segend[0][t];
        carry[1][t] = cacc;
        float q64 = pw[64];
        #pragma unroll
        for (int s2 = 1; s2 <= 6; s2++) {
            cacc = fmaf(q64, cacc, segend[s2][t]);
            carry[s2 + 1][t] = cacc;
        }
    }
    __syncthreads();
    {
        int base = w * 64;
        float cin = (w == 0) ? 0.f : carry[w][lane];
        #pragma unroll 4
        for (int j = 0; j < 64; j++) {
            int l = base + j;
            float tf = fmaf(pw[j + 1], cin, tb[l * 33 + lane]);
            tb[l * 33 + lane] = tf;
            xb[l * 33 + lane] = xb[l * 33 + lane] - tf;
        }
    }
    __syncthreads();
    for (int ci = w; ci < 32; ci += 8) {
        int cc = c0 + ci;
        if (cc >= C_) continue;
        size_t bc = (size_t)b * C_ + cc;
        float* gs = g_s + bc * LP;
        float* gt = g_trend + bc * (size_t)L_;
        for (int l0 = 0; l0 < L_; l0 += 32) {
            gs[l0 + lane] = xb[(l0 + lane) * 33 + ci];
            gt[l0 + lane] = tb[(l0 + lane) * 33 + ci];
        }
        if (lane < 8) gs[L_ + lane] = xb[511 * 33 + ci];
        #pragma unroll
        for (int nn = 0; nn < 2; nn++) {
            int n = 2 * lane + nn;
            float sum = 0.f;
            #pragma unroll
            for (int p = 0; p < 16; p++) {
                int l = n * 8 + p;
                if (l > 511) l = 511;
                sum += xb[l * 33 + ci];
            }
            g_pool[bc * 64 + n] = sum * (1.f / 16.f);
        }
    }
}

// ---------------- K1b: fc1 + gelu -> g_h ([bc][j][n]); bn1 per-n partials ----------------
__global__ void __launch_bounds__(256) k1b_fc1(const float* __restrict__ fc1_w,
                                               const float* __restrict__ fc1_b) {
    __shared__ float s_sm[16 * LP];       // 33280B
    __shared__ float wt[512];             // wt[p*32+j] = fc1_w[j*16+p]
    __shared__ float stage[32 * 65];      // [j][n] padded
    int t = threadIdx.x;
    int w = t >> 5, lane = t & 31;
    size_t bc0 = (size_t)blockIdx.x * 16;
    for (int i = t; i < 512; i += 256) {
        int p = i >> 5, j = i & 31;
        wt[i] = fc1_w[j * 16 + p];
    }
    for (int i = t; i < 16 * LP; i += 256) s_sm[i] = g_s[bc0 * LP + i];
    __syncthreads();
    float wj[16];
    #pragma unroll
    for (int p = 0; p < 16; p++) wj[p] = wt[p * 32 + lane];
    float bj = fc1_b[lane];
    float ps[8], pq[8];
    #pragma unroll
    for (int i = 0; i < 8; i++) { ps[i] = 0.f; pq[i] = 0.f; }

    for (int r = 0; r < 16; r++) {
        const float* sp = s_sm + r * LP;
        #pragma unroll
        for (int nn = 0; nn < 8; nn++) {
            int n = nn * 8 + w;
            const float* pp = sp + n * 8;
            float acc = bj;
            #pragma unroll
            for (int p = 0; p < 16; p++) acc = fmaf(pp[p], wj[p], acc);
            float g = geluf(acc);
            ps[nn] += g;
            pq[nn] = fmaf(g, g, pq[nn]);
            stage[lane * 65 + n] = g;
        }
        __syncthreads();
        float* dst = g_h + (bc0 + r) * 2048;
        for (int i = t; i < 2048; i += 256)
            dst[i] = stage[(i >> 6) * 65 + (i & 63)];
        __syncthreads();
    }
    #pragma unroll
    for (int nn = 0; nn < 8; nn++) {
        float s = ps[nn], q = pq[nn];
        #pragma unroll
        for (int off = 16; off; off >>= 1) {
            s += __shfl_down_sync(0xffffffff, s, off);
            q += __shfl_down_sync(0xffffffff, q, off);
        }
        if (lane == 0) {
            int n = nn * 8 + w;
            g_p1s[blockIdx.x * 64 + n] = s;
            g_p1q[blockIdx.x * 64 + n] = q;
        }
    }
}

// ---------------- K3/K5: reduce bn partials ----------------
__global__ void __launch_bounds__(1024) k3_stats1(const float* __restrict__ bn_w,
                                                  const float* __restrict__ bn_b) {
    __shared__ float ss[1024], qq[1024];
    int t = threadIdx.x;
    int n = t & 63, part = t >> 6;
    float s = 0.f, q = 0.f;
    for (int blk = part; blk < NB1; blk += 16) { s += g_p1s[blk * 64 + n]; q += g_p1q[blk * 64 + n]; }
    ss[t] = s; qq[t] = q;
    __syncthreads();
    if (t < 64) {
        float S = 0.f, Q = 0.f;
        #pragma unroll
        for (int i = 0; i < 16; i++) { S += ss[t + 64 * i]; Q += qq[t + 64 * i]; }
        float inv = 1.f / CNT_BN;
        float mu = S * inv;
        float var = fmaxf(Q * inv - mu * mu, 0.f);
        float sc = bn_w[t] * rsqrtf(var + EPS_);
        g_sc1[t] = sc;
        g_bi1[t] = fmaf(-mu, sc, bn_b[t]);
    }
}
__global__ void __launch_bounds__(1024) k5_stats2(const float* __restrict__ bn_w,
                                                  const float* __restrict__ bn_b) {
    __shared__ float ss[1024], qq[1024];
    int t = threadIdx.x;
    int n = t & 63, part = t >> 6;
    float s = 0.f, q = 0.f;
    for (int blk = part; blk < NB1; blk += 16) { s += g_p2s[blk * 64 + n]; q += g_p2q[blk * 64 + n]; }
    ss[t] = s; qq[t] = q;
    __syncthreads();
    if (t < 64) {
        float S = 0.f, Q = 0.f;
        #pragma unroll
        for (int i = 0; i < 16; i++) { S += ss[t + 64 * i]; Q += qq[t + 64 * i]; }
        float inv = 1.f / CNT_BN;
        float mu = S * inv;
        float var = fmaxf(Q * inv - mu * mu, 0.f);
        float sc = bn_w[t] * rsqrtf(var + EPS_);
        g_sc2[t] = sc;
        g_bi2[t] = fmaf(-mu, sc, bn_b[t]);
    }
}

// ---------------- K4: read g_h, bn1 affine + conv3 + gelu; bn2 partials ----------------
__global__ void __launch_bounds__(256) k4_conv(const float* __restrict__ conv_w,
                                               const float* __restrict__ conv_b) {
    __shared__ float rs[256], rq[256];
    int t = threadIdx.x;
    size_t bc0 = (size_t)blockIdx.x * 16;
    int n = t & 63;
    float sc = g_sc1[n], bi = g_bi1[n];
    float c0 = conv_w[n * 3], c1 = conv_w[n * 3 + 1], c2 = conv_w[n * 3 + 2];
    float cbv = conv_b[n];
    float psum = 0.f, psq = 0.f;
    #pragma unroll
    for (int q = 0; q < 4; q++) {
        int pair = t + 256 * q;
        int row = pair >> 6;
        const float* hp = g_h + (bc0 + row) * 2048 + n;
        float a[34];
        a[0] = 0.f; a[33] = 0.f;
        #pragma unroll
        for (int j = 0; j < 32; j++) a[j + 1] = fmaf(hp[j * 64], sc, bi);
        #pragma unroll
        for (int j = 0; j < 32; j++) {
            float vv = cbv;
            vv = fmaf(a[j], c0, vv);
            vv = fmaf(a[j + 1], c1, vv);
            vv = fmaf(a[j + 2], c2, vv);
            float g = geluf(vv);
            psum += g;
            psq = fmaf(g, g, psq);
        }
    }
    rs[t] = psum; rq[t] = psq;
    __syncthreads();
    if (t < 64) {
        float S = rs[t] + rs[t + 64] + rs[t + 128] + rs[t + 192];
        float Q = rq[t] + rq[t + 64] + rq[t + 128] + rq[t + 192];
        g_p2s[blockIdx.x * 64 + t] = S;
        g_p2q[blockIdx.x * 64 + t] = Q;
    }
}

// ---------------- Kg: gating MLP, warp-per-row, 32 rows/block ----------------
__global__ void __launch_bounds__(256) kg_gate(const float* __restrict__ m1_w,
                                               const float* __restrict__ m1_b,
                                               const float* __restrict__ m2_w,
                                               const float* __restrict__ m2_b) {
    extern __shared__ float kg_sm[];
    float* m1p = kg_sm;                 // 8320
    float* m2t = kg_sm + 8320;          // 8192
    float* ps  = kg_sm + 16512;         // 2048
    float* us  = kg_sm + 18560;         // 1024
    int t = threadIdx.x;
    int w = t >> 5, lane = t & 31;
    size_t bc0 = (size_t)blockIdx.x * 32;
    for (int i = t; i < 8192; i += 256) {
        int h = i >> 6, k = i & 63;
        m1p[h * 65 + k] = m1_w[i];
    }
    for (int i = t; i < 8192; i += 256) {
        int nn = i >> 7, h = i & 127;
        m2t[h * 64 + nn] = m2_w[i];
    }
    for (int i = t; i < 2048; i += 256)
        ps[i] = g_pool[bc0 * 64 + i];
    __syncthreads();
    float* uw = us + w * 128;
    #pragma unroll
    for (int rr = 0; rr < 4; rr++) {
        int rloc = rr * 8 + w;
        const float* pr = ps + rloc * 64;
        float u0 = m1_b[lane], u1 = m1_b[lane + 32], u2 = m1_b[lane + 64], u3 = m1_b[lane + 96];
        #pragma unroll 8
        for (int k = 0; k < 64; k++) {
            float pk = pr[k];
            u0 = fmaf(pk, m1p[lane * 65 + k], u0);
            u1 = fmaf(pk, m1p[(lane + 32) * 65 + k], u1);
            u2 = fmaf(pk, m1p[(lane + 64) * 65 + k], u2);
            u3 = fmaf(pk, m1p[(lane + 96) * 65 + k], u3);
        }
        uw[lane] = geluf(u0);
        uw[lane + 32] = geluf(u1);
        uw[lane + 64] = geluf(u2);
        uw[lane + 96] = geluf(u3);
        __syncwarp();
        float a0 = m2_b[lane], a1 = m2_b[lane + 32];
        #pragma unroll 8
        for (int h = 0; h < 128; h++) {
            float uh = uw[h];
            a0 = fmaf(uh, m2t[h * 64 + lane], a0);
            a1 = fmaf(uh, m2t[h * 64 + lane + 32], a1);
        }
        g_w[(bc0 + rloc) * 64 + lane] = sigf(a0);
        g_w[(bc0 + rloc) * 64 + lane + 32] = sigf(a1);
        __syncwarp();
    }
}

// ---------------- K6: read g_h, chain conv/bn2/fc2 + combine + LN -> g_y (staged stores) ----------------
// dynamic smem: s_sm 16*LP | w2 512 | ystage 4*1088
__global__ void __launch_bounds__(256) k6_local(const float* __restrict__ conv_w,
                                                const float* __restrict__ conv_b,
                                                const float* __restrict__ fc2_w,
                                                const float* __restrict__ fc2_b,
                                                const float* __restrict__ gl_scale,
                                                const float* __restrict__ ln_w,
                                                const float* __restrict__ ln_b) {
    extern __shared__ float k6_sm[];
    float* s_sm = k6_sm;                       // 8320 floats
    float* w2 = k6_sm + 16 * LP;               // 512
    float* ystage = k6_sm + 16 * LP + 512;     // 4*1088 = 4352
    __shared__ float b2[16], lw[16], lb[16];
    int t = threadIdx.x;
    size_t bc0 = (size_t)blockIdx.x * 16;
    w2[t] = fc2_w[t];
    w2[t + 256] = fc2_w[t + 256];
    if (t < 16) { b2[t] = fc2_b[t]; lw[t] = ln_w[t]; lb[t] = ln_b[t]; }
    for (int i = t; i < 16 * LP; i += 256) s_sm[i] = g_s[bc0 * LP + i];
    __syncthreads();
    float gs = gl_scale[0];
    int n = t & 63;
    float sc1v = g_sc1[n], bi1v = g_bi1[n];
    float sc2v = g_sc2[n], bi2v = g_bi2[n];
    float c0 = conv_w[n * 3], c1 = conv_w[n * 3 + 1], c2 = conv_w[n * 3 + 2];
    float cbv = conv_b[n];
    #pragma unroll
    for (int q = 0; q < 4; q++) {
        int pair = t + 256 * q;
        int row = pair >> 6;
        int r4 = row & 3;
        size_t bc = bc0 + row;
        const float* hp = g_h + bc * 2048 + n;
        float a[34];
        a[0] = 0.f; a[33] = 0.f;
        #pragma unroll
        for (int j = 0; j < 32; j++) a[j + 1] = fmaf(hp[j * 64], sc1v, bi1v);
        float left = 0.f;
        #pragma unroll
        for (int j = 0; j < 32; j++) {
            float cur = a[j + 1];
            float vv = cbv;
            vv = fmaf(left, c0, vv);
            vv = fmaf(cur, c1, vv);
            vv = fmaf(a[j + 2], c2, vv);
            left = cur;
            a[j + 1] = fmaf(geluf(vv), sc2v, bi2v);
        }
        float p[16];
        const float4* spp = (const float4*)(s_sm + row * LP + n * 8);
        #pragma unroll
        for (int v = 0; v < 4; v++) {
            float4 f = spp[v];
            p[4 * v] = f.x; p[4 * v + 1] = f.y; p[4 * v + 2] = f.z; p[4 * v + 3] = f.w;
        }
        float wv = g_w[bc * 64 + n];
        float m3 = fmaf(gs, wv, 3.f);
        float y[16];
        float musum = 0.f;
        #pragma unroll
        for (int pp = 0; pp < 16; pp++) {
            float acc = b2[pp];
            const float4* wp = (const float4*)(w2 + pp * 32);
            #pragma unroll
            for (int j = 0; j < 8; j++) {
                float4 f = wp[j];
                acc = fmaf(a[4 * j + 1], f.x, acc);
                acc = fmaf(a[4 * j + 2], f.y, acc);
                acc = fmaf(a[4 * j + 3], f.z, acc);
                acc = fmaf(a[4 * j + 4], f.w, acc);
            }
            float yy = fmaf(p[pp], m3, acc);
            y[pp] = yy;
            musum += yy;
        }
        float mu = musum * (1.f / 16.f);
        float s2 = 0.f;
        #pragma unroll
        for (int pp = 0; pp < 16; pp++) { float d = y[pp] - mu; s2 = fmaf(d, d, s2); }
        float r = rsqrtf(s2 * (1.f / 16.f) + EPS_);
        // stage LN output: ystage[r4][n*17 + p] (conflict-free lanes)
        float* yst = ystage + r4 * 1088 + n * 17;
        #pragma unroll
        for (int pp = 0; pp < 16; pp++)
            yst[pp] = fmaf((y[pp] - mu) * r, lw[pp], lb[pp]);
        __syncthreads();
        // coalesced flush: 4 rows x 1024 floats
        {
            float* gyb = g_y + (bc0 + (size_t)q * 4) * 1024;
            for (int i = t; i < 4096; i += 256) {
                int rr = i >> 10, k = i & 1023;
                gyb[rr * 1024 + k] = ystage[rr * 1088 + (k >> 4) * 17 + (k & 15)];
            }
        }
        __syncthreads();
    }
}

// ---------------- K7: fused final GEMM + un-RevIN + transpose ----------------
// 321 blocks; block tile 64 rows x 96 cols; 128 threads; thread tile 8x6
// As row-major [64][20] (coalesced cp.async.16 loads; broadcast LDS reads)
__global__ void __launch_bounds__(128) k7_gemm(const float* __restrict__ rev_w,
                                               const float* __restrict__ rev_b,
                                               float* __restrict__ out) {
    __shared__ float As[2][64 * 20];
    __shared__ float Bs[2][16 * 96];
    int t = threadIdx.x;
    size_t bc0 = (size_t)blockIdx.x * 64;
    int ty = t >> 4, tx = t & 15;
    int r0 = ty * 8, c0l = tx * 6;

    int lr = t >> 1, lk = (t & 1) * 8;               // As: row lr (0..63), 8 contiguous k
    int bk = t >> 3, bo = (t & 7) * 12;              // Bs: k-row bk (0..15), 12 floats

    uint32_t as_sm[2], bs_sm[2];
    as_sm[0] = (uint32_t)__cvta_generic_to_shared(&As[0][0]);
    as_sm[1] = (uint32_t)__cvta_generic_to_shared(&As[1][0]);
    bs_sm[0] = (uint32_t)__cvta_generic_to_shared(&Bs[0][0]);
    bs_sm[1] = (uint32_t)__cvta_generic_to_shared(&Bs[1][0]);

    float acc[8][6];
    #pragma unroll
    for (int i = 0; i < 8; i++)
        #pragma unroll
        for (int j = 0; j < 6; j++) acc[i][j] = 0.f;

    auto load_tile = [&](int it, int bu) {
        int k0 = it * 16;
        const float* srcrow;
        if (k0 < 1024) srcrow = g_y + (bc0 + lr) * 1024 + k0 + lk;
        else           srcrow = g_trend + (bc0 + lr) * 512 + (k0 - 1024) + lk;
        uint32_t d = as_sm[bu] + (uint32_t)((lr * 20 + lk) * 4);
        cpa16(d, srcrow);
        cpa16(d + 16, srcrow + 4);
        const float* bsrc = g_Wt + (k0 + bk) * 96 + bo;
        #pragma unroll
        for (int i = 0; i < 3; i++)
            cpa16(bs_sm[bu] + (uint32_t)((bk * 96 + bo + 4 * i) * 4), bsrc + 4 * i);
    };

    load_tile(0, 0);
    cp_commit();
    for (int it = 0; it < 96; it++) {
        int cur = it & 1;
        if (it + 1 < 96) {
            load_tile(it + 1, cur ^ 1);
            cp_commit();
            asm volatile("cp.async.wait_group 1;\n" ::: "memory");
        } else {
            asm volatile("cp.async.wait_group 0;\n" ::: "memory");
        }
        __syncthreads();
        #pragma unroll
        for (int k = 0; k < 16; k++) {
            float a8[8];
            #pragma unroll
            for (int i = 0; i < 8; i++) a8[i] = As[cur][(r0 + i) * 20 + k];
            const float* bp = &Bs[cur][k * 96 + c0l];
            float b6[6];
            #pragma unroll
            for (int j = 0; j < 6; j++) b6[j] = bp[j];
            #pragma unroll
            for (int i = 0; i < 8; i++)
                #pragma unroll
                for (int j = 0; j < 6; j++)
                    acc[i][j] = fmaf(a8[i], b6[j], acc[i][j]);
        }
        __syncthreads();
    }
    #pragma unroll
    for (int i = 0; i < 8; i++) {
        size_t bc = bc0 + r0 + i;
        int b = (int)(bc / C_);
        int c = (int)(bc - (size_t)b * C_);
        float rw = rev_w[c], rb = rev_b[c];
        float sd = g_std[bc], mn = g_mean[bc];
        #pragma unroll
        for (int j = 0; j < 6; j++) {
            int col = c0l + j;
            float v = acc[i][j] + g_cb[col];
            v = fmaf((v - rb) / rw, sd, mn);
            out[((size_t)b * PRED_ + col) * C_ + c] = v;
        }
    }
}

// ---------------- launch ----------------
extern "C" void kernel_launch(void* const* d_in, const int* in_sizes, int n_in,
                              void* d_out, int out_size) {
    const float* x       = (const float*)d_in[0];
    const float* rev_w   = (const float*)d_in[1];
    const float* rev_b   = (const float*)d_in[2];
    const float* fc1_w   = (const float*)d_in[3];
    const float* fc1_b   = (const float*)d_in[4];
    const float* bn1_w   = (const float*)d_in[5];
    const float* bn1_b   = (const float*)d_in[6];
    const float* conv_w  = (const float*)d_in[7];
    const float* conv_b  = (const float*)d_in[8];
    const float* bn2_w   = (const float*)d_in[9];
    const float* bn2_b   = (const float*)d_in[10];
    const float* fc2_w   = (const float*)d_in[11];
    const float* fc2_b   = (const float*)d_in[12];
    const float* m1_w    = (const float*)d_in[13];
    const float* m1_b    = (const float*)d_in[14];
    const float* m2_w    = (const float*)d_in[15];
    const float* m2_b    = (const float*)d_in[16];
    const float* gl_sc   = (const float*)d_in[17];
    const float* ln_w    = (const float*)d_in[18];
    const float* ln_b    = (const float*)d_in[19];
    const float* seas_w  = (const float*)d_in[20];
    const float* seas_b  = (const float*)d_in[21];
    const float* tr_w    = (const float*)d_in[22];
    const float* tr_b    = (const float*)d_in[23];
    const float* fus_w   = (const float*)d_in[24];
    const float* fus_b   = (const float*)d_in[25];
    float* out = (float*)d_out;

    const int K1_SMEM = 512 * 33 * 2 * sizeof(float);   // 135168
    const int KG_SMEM = 19584 * sizeof(float);           // 78336
    const int K6_SMEM = (16 * LP + 512 + 4 * 1088) * sizeof(float);  // 52752 -> pad
    cudaFuncSetAttribute(k1a_prep, cudaFuncAttributeMaxDynamicSharedMemorySize, K1_SMEM);
    cudaFuncSetAttribute(kg_gate, cudaFuncAttributeMaxDynamicSharedMemorySize, KG_SMEM);
    cudaFuncSetAttribute(k6_local, cudaFuncAttributeMaxDynamicSharedMemorySize, K6_SMEM);

    k1a_prep<<<dim3(11, 64), 256, K1_SMEM>>>(x, rev_w, rev_b);   // 1
    k0_fold1<<<384, 256>>>(seas_w, fus_w);                        // 2
    k0_fold2<<<192, 256>>>(tr_w, fus_w);                          // 3
    k1b_fc1<<<NB1, 256>>>(fc1_w, fc1_b);                          // 4 -> profiled
    k3_stats1<<<1, 1024>>>(bn1_w, bn1_b);
    k4_conv<<<NB1, 256>>>(conv_w, conv_b);
    k5_stats2<<<1, 1024>>>(bn2_w, bn2_b);
    kg_gate<<<642, 256, KG_SMEM>>>(m1_w, m1_b, m2_w, m2_b);
    k6_local<<<NB1, 256, K6_SMEM>>>(conv_w, conv_b, fc2_w, fc2_b, gl_sc, ln_w, ln_b);
    k0_cb<<<1, 96>>>(fus_w, fus_b, seas_b, tr_b);
    k7_gemm<<<321, 128>>>(rev_w, rev_b, out);
    (void)in_sizes; (void)n_in; (void)out_size;
}